// round 1
// baseline (speedup 1.0000x reference)
#include <cuda_runtime.h>

#define D_MODEL 1024
#define NHEAD   16
#define DK      64
#define BATCH   2
#define SEQ     2048
#define TOKENS  (BATCH * SEQ)   // 4096

// ---------------- scratch (device globals; no allocations allowed) ----------
__device__ float g_Qh[BATCH * NHEAD * SEQ * DK];   // [B,H,S,dk]
__device__ float g_Kh[BATCH * NHEAD * SEQ * DK];
__device__ float g_Vh[BATCH * NHEAD * SEQ * DK];
__device__ float g_ctx[TOKENS * D_MODEL];          // [B,S,D] attention output

// ============================================================================
// Fused QKV projection: Y = X @ W^T + b, written in head-major layout.
// Tiled SGEMM: BM=64, BN=64, BK=16, 256 threads, 4x4 per thread.
// blockIdx.z selects q/k/v.
// ============================================================================
__global__ __launch_bounds__(256) void qkv_proj_kernel(
    const float* __restrict__ q,  const float* __restrict__ k,  const float* __restrict__ v,
    const float* __restrict__ Wq, const float* __restrict__ bq,
    const float* __restrict__ Wk, const float* __restrict__ bk,
    const float* __restrict__ Wv, const float* __restrict__ bv)
{
    const float* X; const float* W; const float* bias; float* Y;
    if (blockIdx.z == 0)      { X = q; W = Wq; bias = bq; Y = g_Qh; }
    else if (blockIdx.z == 1) { X = k; W = Wk; bias = bk; Y = g_Kh; }
    else                      { X = v; W = Wv; bias = bv; Y = g_Vh; }

    __shared__ float As[16][64];   // [k][m]
    __shared__ float Bs[16][64];   // [k][n]

    const int tid = threadIdx.x;
    const int tx = tid & 15;       // n group
    const int ty = tid >> 4;       // m group
    const int m0 = blockIdx.y * 64;
    const int n0 = blockIdx.x * 64;

    const int lr = tid >> 2;        // 0..63
    const int lc = (tid & 3) * 4;   // 0,4,8,12

    float acc[4][4] = {};

    for (int k0 = 0; k0 < D_MODEL; k0 += 16) {
        float4 a = *(const float4*)&X[(size_t)(m0 + lr) * D_MODEL + k0 + lc];
        float4 b = *(const float4*)&W[(size_t)(n0 + lr) * D_MODEL + k0 + lc];
        As[lc + 0][lr] = a.x; As[lc + 1][lr] = a.y; As[lc + 2][lr] = a.z; As[lc + 3][lr] = a.w;
        Bs[lc + 0][lr] = b.x; Bs[lc + 1][lr] = b.y; Bs[lc + 2][lr] = b.z; Bs[lc + 3][lr] = b.w;
        __syncthreads();
        #pragma unroll
        for (int kk = 0; kk < 16; kk++) {
            float4 ra = *(const float4*)&As[kk][ty * 4];
            float4 rb = *(const float4*)&Bs[kk][tx * 4];
            acc[0][0] += ra.x * rb.x; acc[0][1] += ra.x * rb.y; acc[0][2] += ra.x * rb.z; acc[0][3] += ra.x * rb.w;
            acc[1][0] += ra.y * rb.x; acc[1][1] += ra.y * rb.y; acc[1][2] += ra.y * rb.z; acc[1][3] += ra.y * rb.w;
            acc[2][0] += ra.z * rb.x; acc[2][1] += ra.z * rb.y; acc[2][2] += ra.z * rb.z; acc[2][3] += ra.z * rb.w;
            acc[3][0] += ra.w * rb.x; acc[3][1] += ra.w * rb.y; acc[3][2] += ra.w * rb.z; acc[3][3] += ra.w * rb.w;
        }
        __syncthreads();
    }

    // Epilogue: head-major write. BN=64 => this block covers exactly one head.
    const int h = n0 >> 6;                 // head index
    float4 bb = *(const float4*)&bias[n0 + tx * 4];
    #pragma unroll
    for (int i = 0; i < 4; i++) {
        int m = m0 + ty * 4 + i;
        int b_idx = m >> 11;               // batch
        int s_idx = m & 2047;              // seq pos
        float4 o;
        o.x = acc[i][0] + bb.x;
        o.y = acc[i][1] + bb.y;
        o.z = acc[i][2] + bb.z;
        o.w = acc[i][3] + bb.w;
        size_t base = (((size_t)b_idx * NHEAD + h) * SEQ + s_idx) * DK + tx * 4;
        *(float4*)&Y[base] = o;
    }
}

// ============================================================================
// Flash attention (fp32, online softmax). One block = 64 queries of one (b,h).
// Q and K stored TRANSPOSED in smem ([d][row]) for conflict-free float4 reads.
// 256 threads, 4x4 register tiling in both QK^T and PV phases.
// ============================================================================
#define ALD 68   // smem leading dim (pad: 68 % 32 = 4 -> conflict-free, 16B aligned)

__global__ __launch_bounds__(256) void attn_kernel()
{
    extern __shared__ float sm[];
    float* Qts = sm;                 // [64 d][64 row], scaled by 1/8
    float* Kts = sm + 64 * ALD;      // [64 d][64 key]
    float* Vs  = sm + 2 * 64 * ALD;  // [64 key][64 dv]
    float* Ps  = sm + 3 * 64 * ALD;  // [64 row][64 key]

    const int tid = threadIdx.x;
    const int tx = tid & 15;
    const int ty = tid >> 4;
    const int bh = blockIdx.y;                 // b*16 + h
    const int q0 = blockIdx.x * 64;

    const float* Qb = g_Qh + ((size_t)bh * SEQ + q0) * DK;
    const float* Kb = g_Kh + (size_t)bh * SEQ * DK;
    const float* Vb = g_Vh + (size_t)bh * SEQ * DK;

    const int lr = tid >> 2;        // 0..63
    const int lc = (tid & 3) * 4;   // 0,4,8,12

    // Load Q tile, transposed + pre-scaled by 1/sqrt(dk) = 0.125
    #pragma unroll
    for (int c = 0; c < DK; c += 16) {
        float4 t = *(const float4*)&Qb[(size_t)lr * DK + lc + c];
        Qts[(lc + c + 0) * ALD + lr] = t.x * 0.125f;
        Qts[(lc + c + 1) * ALD + lr] = t.y * 0.125f;
        Qts[(lc + c + 2) * ALD + lr] = t.z * 0.125f;
        Qts[(lc + c + 3) * ALD + lr] = t.w * 0.125f;
    }

    float m_i[4], l_i[4], acc[4][4];
    #pragma unroll
    for (int i = 0; i < 4; i++) {
        m_i[i] = -1e30f; l_i[i] = 0.0f;
        #pragma unroll
        for (int j = 0; j < 4; j++) acc[i][j] = 0.0f;
    }

    for (int k0 = 0; k0 < SEQ; k0 += 64) {
        // Load K (transposed) and V (natural) tiles
        #pragma unroll
        for (int c = 0; c < DK; c += 16) {
            float4 t = *(const float4*)&Kb[(size_t)(k0 + lr) * DK + lc + c];
            Kts[(lc + c + 0) * ALD + lr] = t.x;
            Kts[(lc + c + 1) * ALD + lr] = t.y;
            Kts[(lc + c + 2) * ALD + lr] = t.z;
            Kts[(lc + c + 3) * ALD + lr] = t.w;
            float4 u = *(const float4*)&Vb[(size_t)(k0 + lr) * DK + lc + c];
            *(float4*)&Vs[lr * ALD + lc + c] = u;
        }
        __syncthreads();

        // S = Q K^T  (rows ty*4+i, cols tx*4+j)
        float s[4][4] = {};
        #pragma unroll
        for (int d = 0; d < DK; d++) {
            float4 qa = *(const float4*)&Qts[d * ALD + ty * 4];
            float4 kb = *(const float4*)&Kts[d * ALD + tx * 4];
            s[0][0] += qa.x * kb.x; s[0][1] += qa.x * kb.y; s[0][2] += qa.x * kb.z; s[0][3] += qa.x * kb.w;
            s[1][0] += qa.y * kb.x; s[1][1] += qa.y * kb.y; s[1][2] += qa.y * kb.z; s[1][3] += qa.y * kb.w;
            s[2][0] += qa.z * kb.x; s[2][1] += qa.z * kb.y; s[2][2] += qa.z * kb.z; s[2][3] += qa.z * kb.w;
            s[3][0] += qa.w * kb.x; s[3][1] += qa.w * kb.y; s[3][2] += qa.w * kb.z; s[3][3] += qa.w * kb.w;
        }

        // Online softmax per row (reduce across the 16 tx lanes of each row)
        #pragma unroll
        for (int i = 0; i < 4; i++) {
            float mx = fmaxf(fmaxf(s[i][0], s[i][1]), fmaxf(s[i][2], s[i][3]));
            mx = fmaxf(mx, __shfl_xor_sync(0xffffffffu, mx, 1));
            mx = fmaxf(mx, __shfl_xor_sync(0xffffffffu, mx, 2));
            mx = fmaxf(mx, __shfl_xor_sync(0xffffffffu, mx, 4));
            mx = fmaxf(mx, __shfl_xor_sync(0xffffffffu, mx, 8));
            float mnew = fmaxf(m_i[i], mx);
            float corr = __expf(m_i[i] - mnew);
            float rs = 0.0f;
            #pragma unroll
            for (int j = 0; j < 4; j++) { s[i][j] = __expf(s[i][j] - mnew); rs += s[i][j]; }
            rs += __shfl_xor_sync(0xffffffffu, rs, 1);
            rs += __shfl_xor_sync(0xffffffffu, rs, 2);
            rs += __shfl_xor_sync(0xffffffffu, rs, 4);
            rs += __shfl_xor_sync(0xffffffffu, rs, 8);
            l_i[i] = l_i[i] * corr + rs;
            m_i[i] = mnew;
            #pragma unroll
            for (int j = 0; j < 4; j++) acc[i][j] *= corr;
            *(float4*)&Ps[(ty * 4 + i) * ALD + tx * 4] = make_float4(s[i][0], s[i][1], s[i][2], s[i][3]);
        }
        __syncthreads();

        // O += P @ V   (rows ty*4+i, dv cols tx*4+j)
        #pragma unroll 8
        for (int kk = 0; kk < 64; kk++) {
            float4 vv = *(const float4*)&Vs[kk * ALD + tx * 4];
            float p0 = Ps[(ty * 4 + 0) * ALD + kk];
            float p1 = Ps[(ty * 4 + 1) * ALD + kk];
            float p2 = Ps[(ty * 4 + 2) * ALD + kk];
            float p3 = Ps[(ty * 4 + 3) * ALD + kk];
            acc[0][0] += p0 * vv.x; acc[0][1] += p0 * vv.y; acc[0][2] += p0 * vv.z; acc[0][3] += p0 * vv.w;
            acc[1][0] += p1 * vv.x; acc[1][1] += p1 * vv.y; acc[1][2] += p1 * vv.z; acc[1][3] += p1 * vv.w;
            acc[2][0] += p2 * vv.x; acc[2][1] += p2 * vv.y; acc[2][2] += p2 * vv.z; acc[2][3] += p2 * vv.w;
            acc[3][0] += p3 * vv.x; acc[3][1] += p3 * vv.y; acc[3][2] += p3 * vv.z; acc[3][3] += p3 * vv.w;
        }
        __syncthreads();
    }

    // Epilogue: normalize and write into [B,S,D] context layout
    const int b_idx = bh >> 4;
    const int h     = bh & 15;
    #pragma unroll
    for (int i = 0; i < 4; i++) {
        float inv = 1.0f / l_i[i];
        int srow = q0 + ty * 4 + i;
        float4 o = make_float4(acc[i][0] * inv, acc[i][1] * inv, acc[i][2] * inv, acc[i][3] * inv);
        size_t base = ((size_t)b_idx * SEQ + srow) * D_MODEL + h * DK + tx * 4;
        *(float4*)&g_ctx[base] = o;
    }
}

// ============================================================================
// Output projection: out = ctx @ Wo^T + bo   (plain [B,S,D] layout)
// ============================================================================
__global__ __launch_bounds__(256) void out_proj_kernel(
    const float* __restrict__ Wo, const float* __restrict__ bo, float* __restrict__ out)
{
    __shared__ float As[16][64];
    __shared__ float Bs[16][64];

    const int tid = threadIdx.x;
    const int tx = tid & 15;
    const int ty = tid >> 4;
    const int m0 = blockIdx.y * 64;
    const int n0 = blockIdx.x * 64;

    const int lr = tid >> 2;
    const int lc = (tid & 3) * 4;

    float acc[4][4] = {};

    for (int k0 = 0; k0 < D_MODEL; k0 += 16) {
        float4 a = *(const float4*)&g_ctx[(size_t)(m0 + lr) * D_MODEL + k0 + lc];
        float4 b = *(const float4*)&Wo[(size_t)(n0 + lr) * D_MODEL + k0 + lc];
        As[lc + 0][lr] = a.x; As[lc + 1][lr] = a.y; As[lc + 2][lr] = a.z; As[lc + 3][lr] = a.w;
        Bs[lc + 0][lr] = b.x; Bs[lc + 1][lr] = b.y; Bs[lc + 2][lr] = b.z; Bs[lc + 3][lr] = b.w;
        __syncthreads();
        #pragma unroll
        for (int kk = 0; kk < 16; kk++) {
            float4 ra = *(const float4*)&As[kk][ty * 4];
            float4 rb = *(const float4*)&Bs[kk][tx * 4];
            acc[0][0] += ra.x * rb.x; acc[0][1] += ra.x * rb.y; acc[0][2] += ra.x * rb.z; acc[0][3] += ra.x * rb.w;
            acc[1][0] += ra.y * rb.x; acc[1][1] += ra.y * rb.y; acc[1][2] += ra.y * rb.z; acc[1][3] += ra.y * rb.w;
            acc[2][0] += ra.z * rb.x; acc[2][1] += ra.z * rb.y; acc[2][2] += ra.z * rb.z; acc[2][3] += ra.z * rb.w;
            acc[3][0] += ra.w * rb.x; acc[3][1] += ra.w * rb.y; acc[3][2] += ra.w * rb.z; acc[3][3] += ra.w * rb.w;
        }
        __syncthreads();
    }

    float4 bb = *(const float4*)&bo[n0 + tx * 4];
    #pragma unroll
    for (int i = 0; i < 4; i++) {
        int m = m0 + ty * 4 + i;
        float4 o;
        o.x = acc[i][0] + bb.x;
        o.y = acc[i][1] + bb.y;
        o.z = acc[i][2] + bb.z;
        o.w = acc[i][3] + bb.w;
        *(float4*)&out[(size_t)m * D_MODEL + n0 + tx * 4] = o;
    }
}

// ============================================================================
// Launch
// ============================================================================
extern "C" void kernel_launch(void* const* d_in, const int* in_sizes, int n_in,
                              void* d_out, int out_size)
{
    const float* q  = (const float*)d_in[0];
    const float* k  = (const float*)d_in[1];
    const float* v  = (const float*)d_in[2];
    const float* Wq = (const float*)d_in[3];
    const float* bq = (const float*)d_in[4];
    const float* Wk = (const float*)d_in[5];
    const float* bk = (const float*)d_in[6];
    const float* Wv = (const float*)d_in[7];
    const float* bv = (const float*)d_in[8];
    const float* Wo = (const float*)d_in[9];
    const float* bo = (const float*)d_in[10];
    float* out = (float*)d_out;

    const int attn_smem = 4 * 64 * ALD * (int)sizeof(float);  // 69632 B
    cudaFuncSetAttribute(attn_kernel, cudaFuncAttributeMaxDynamicSharedMemorySize, attn_smem);

    dim3 gproj(D_MODEL / 64, TOKENS / 64, 3);
    qkv_proj_kernel<<<gproj, 256>>>(q, k, v, Wq, bq, Wk, bk, Wv, bv);

    dim3 gattn(SEQ / 64, BATCH * NHEAD);
    attn_kernel<<<gattn, 256, attn_smem>>>();

    dim3 gout(D_MODEL / 64, TOKENS / 64);
    out_proj_kernel<<<gout, 256>>>(Wo, bo, out);
}

// round 3
// speedup vs baseline: 1.6886x; 1.6886x over previous
#include <cuda_runtime.h>
#include <cstdint>

#define D_MODEL 1024
#define NHEAD   16
#define DK      64
#define BATCH   2
#define SEQ     2048
#define TOKENS  (BATCH * SEQ)   // 4096

// ---------------- scratch (device globals; no allocations allowed) ----------
__device__ float g_Qh[BATCH * NHEAD * SEQ * DK];   // [B,H,S,dk]
__device__ float g_Kh[BATCH * NHEAD * SEQ * DK];
__device__ float g_Vh[BATCH * NHEAD * SEQ * DK];
__device__ float g_ctx[TOKENS * D_MODEL];          // [B,S,D] attention output

// ============================================================================
// Helpers (all plain sm_80-era PTX — no "a"-suffix features)
// ============================================================================
__device__ __forceinline__ uint32_t smem_u32(const void* p) {
    uint32_t a;
    asm("{ .reg .u64 t; cvta.to.shared.u64 t, %1; cvt.u32.u64 %0, t; }" : "=r"(a) : "l"(p));
    return a;
}
__device__ __forceinline__ uint32_t f2tf32(float f) {
    uint32_t u;
    asm("cvt.rna.tf32.f32 %0, %1;" : "=r"(u) : "f"(f));
    return u;
}
__device__ __forceinline__ void cp16(uint32_t dst, const void* src) {
    asm volatile("cp.async.cg.shared.global [%0], [%1], 16;" :: "r"(dst), "l"(src));
}
#define CP_COMMIT() asm volatile("cp.async.commit_group;" ::: "memory")
#define CP_WAIT1()  asm volatile("cp.async.wait_group 1;" ::: "memory")
#define CP_WAIT0()  asm volatile("cp.async.wait_group 0;" ::: "memory")

__device__ __forceinline__ void mma_m16n8k8(float* d, const uint32_t* a, const uint32_t* b) {
    asm volatile(
        "mma.sync.aligned.m16n8k8.row.col.f32.tf32.tf32.f32 "
        "{%0,%1,%2,%3}, {%4,%5,%6,%7}, {%8,%9}, {%0,%1,%2,%3};"
        : "+f"(d[0]), "+f"(d[1]), "+f"(d[2]), "+f"(d[3])
        : "r"(a[0]), "r"(a[1]), "r"(a[2]), "r"(a[3]), "r"(b[0]), "r"(b[1]));
}

// ============================================================================
// tf32 mma.sync GEMM core: acc = A[m0:+128, :1024] @ B[n0:+128, :1024]^T
// BM=BN=128, BK=32, 256 threads, warp grid 2(m) x 4(n), warp tile 64x32.
// Smem: row stride 36 floats (conflict-free fragment loads: bank = 4r+c).
// Double-buffered via cp.async.
// ============================================================================
#define SMEM_STRIDE 36
#define BUF_FLOATS  (128 * SMEM_STRIDE)       // 4608 floats = 18432 B
#define GEMM_SMEM   (4 * BUF_FLOATS * 4)      // A0 A1 B0 B1 = 73728 B

__device__ __forceinline__ void gemm_issue(
    const float* __restrict__ A, const float* __restrict__ B,
    int m0, int n0, int c, int buf, uint32_t sbase, int r0, int c4)
{
    const float* Asrc = A + (size_t)(m0 + r0) * D_MODEL + c * 32 + c4 * 4;
    const float* Bsrc = B + (size_t)(n0 + r0) * D_MODEL + c * 32 + c4 * 4;
    uint32_t dA = sbase + (uint32_t)((buf * BUF_FLOATS + r0 * SMEM_STRIDE + c4 * 4) * 4);
    uint32_t dB = dA + 2 * BUF_FLOATS * 4;
    #pragma unroll
    for (int i = 0; i < 4; i++) {
        cp16(dA + i * (32 * SMEM_STRIDE * 4), Asrc + (size_t)i * 32 * D_MODEL);
        cp16(dB + i * (32 * SMEM_STRIDE * 4), Bsrc + (size_t)i * 32 * D_MODEL);
    }
}

__device__ __forceinline__ void gemm_tf32(
    const float* __restrict__ A, const float* __restrict__ B,
    int m0, int n0, float acc[4][4][4])
{
    extern __shared__ float smf[];
    const uint32_t sbase = smem_u32(smf);
    const int tid  = threadIdx.x;
    const int lane = tid & 31;
    const int wid  = tid >> 5;
    const int warp_m = wid >> 2;     // 0..1  (64 rows each)
    const int warp_n = wid & 3;      // 0..3  (32 cols each)
    const int r0 = tid >> 3;         // gmem load row 0..31
    const int c4 = tid & 7;          // gmem load float4 slot

    #pragma unroll
    for (int mi = 0; mi < 4; mi++)
        #pragma unroll
        for (int ni = 0; ni < 4; ni++)
            #pragma unroll
            for (int r = 0; r < 4; r++) acc[mi][ni][r] = 0.0f;

    gemm_issue(A, B, m0, n0, 0, 0, sbase, r0, c4);
    CP_COMMIT();

    const float* pAbase = smf + (warp_m * 64 + (lane >> 2)) * SMEM_STRIDE + (lane & 3);
    const float* pBbase = smf + 2 * BUF_FLOATS + (warp_n * 32 + (lane >> 2)) * SMEM_STRIDE + (lane & 3);

    #pragma unroll 1
    for (int c = 0; c < D_MODEL / 32; c++) {
        if (c < D_MODEL / 32 - 1) {
            gemm_issue(A, B, m0, n0, c + 1, (c + 1) & 1, sbase, r0, c4);
            CP_COMMIT();
            CP_WAIT1();
        } else {
            CP_WAIT0();
        }
        __syncthreads();

        const float* pA = pAbase + (c & 1) * BUF_FLOATS;
        const float* pB = pBbase + (c & 1) * BUF_FLOATS;

        #pragma unroll
        for (int ki = 0; ki < 4; ki++) {
            uint32_t af[4][4], bf[4][2];
            #pragma unroll
            for (int mi = 0; mi < 4; mi++) {
                int base = mi * (16 * SMEM_STRIDE) + ki * 8;
                af[mi][0] = f2tf32(pA[base]);
                af[mi][1] = f2tf32(pA[base + 8 * SMEM_STRIDE]);
                af[mi][2] = f2tf32(pA[base + 4]);
                af[mi][3] = f2tf32(pA[base + 8 * SMEM_STRIDE + 4]);
            }
            #pragma unroll
            for (int ni = 0; ni < 4; ni++) {
                int base = ni * (8 * SMEM_STRIDE) + ki * 8;
                bf[ni][0] = f2tf32(pB[base]);
                bf[ni][1] = f2tf32(pB[base + 4]);
            }
            #pragma unroll
            for (int mi = 0; mi < 4; mi++)
                #pragma unroll
                for (int ni = 0; ni < 4; ni++)
                    mma_m16n8k8(acc[mi][ni], af[mi], bf[ni]);
        }
        __syncthreads();
    }
}

// ============================================================================
// QKV projection: Y = X @ W^T + b, head-major output [B,H,S,dk]
// ============================================================================
__global__ __launch_bounds__(256) void qkv_tc_kernel(
    const float* __restrict__ q,  const float* __restrict__ k,  const float* __restrict__ v,
    const float* __restrict__ Wq, const float* __restrict__ bq,
    const float* __restrict__ Wk, const float* __restrict__ bk,
    const float* __restrict__ Wv, const float* __restrict__ bv)
{
    const float* X; const float* W; const float* bias; float* Y;
    if (blockIdx.z == 0)      { X = q; W = Wq; bias = bq; Y = g_Qh; }
    else if (blockIdx.z == 1) { X = k; W = Wk; bias = bk; Y = g_Kh; }
    else                      { X = v; W = Wv; bias = bv; Y = g_Vh; }

    const int m0 = blockIdx.y * 128;
    const int n0 = blockIdx.x * 128;

    float acc[4][4][4];
    gemm_tf32(X, W, m0, n0, acc);

    const int tid  = threadIdx.x;
    const int lane = tid & 31;
    const int wid  = tid >> 5;
    const int warp_m = wid >> 2;
    const int warp_n = wid & 3;
    const int h = (n0 + warp_n * 32) >> 6;     // warp's 32 cols sit in one head

    #pragma unroll
    for (int mi = 0; mi < 4; mi++) {
        int m_lo = m0 + warp_m * 64 + mi * 16 + (lane >> 2);
        int m_hi = m_lo + 8;
        float* row_lo = Y + (((size_t)(m_lo >> 11) * NHEAD + h) * SEQ + (m_lo & 2047)) * DK;
        float* row_hi = Y + (((size_t)(m_hi >> 11) * NHEAD + h) * SEQ + (m_hi & 2047)) * DK;
        #pragma unroll
        for (int ni = 0; ni < 4; ni++) {
            int colg = n0 + warp_n * 32 + ni * 8 + (lane & 3) * 2;
            float2 bb = *(const float2*)&bias[colg];
            int dkc = colg & 63;
            *(float2*)&row_lo[dkc] = make_float2(acc[mi][ni][0] + bb.x, acc[mi][ni][1] + bb.y);
            *(float2*)&row_hi[dkc] = make_float2(acc[mi][ni][2] + bb.x, acc[mi][ni][3] + bb.y);
        }
    }
}

// ============================================================================
// Output projection: out = ctx @ Wo^T + bo   ([B,S,D] layout)
// ============================================================================
__global__ __launch_bounds__(256) void out_tc_kernel(
    const float* __restrict__ Wo, const float* __restrict__ bo, float* __restrict__ out)
{
    const int m0 = blockIdx.y * 128;
    const int n0 = blockIdx.x * 128;

    float acc[4][4][4];
    gemm_tf32(g_ctx, Wo, m0, n0, acc);

    const int tid  = threadIdx.x;
    const int lane = tid & 31;
    const int wid  = tid >> 5;
    const int warp_m = wid >> 2;
    const int warp_n = wid & 3;

    #pragma unroll
    for (int mi = 0; mi < 4; mi++) {
        int m_lo = m0 + warp_m * 64 + mi * 16 + (lane >> 2);
        float* row_lo = out + (size_t)m_lo * D_MODEL;
        float* row_hi = row_lo + 8 * D_MODEL;
        #pragma unroll
        for (int ni = 0; ni < 4; ni++) {
            int colg = n0 + warp_n * 32 + ni * 8 + (lane & 3) * 2;
            float2 bb = *(const float2*)&bo[colg];
            *(float2*)&row_lo[colg] = make_float2(acc[mi][ni][0] + bb.x, acc[mi][ni][1] + bb.y);
            *(float2*)&row_hi[colg] = make_float2(acc[mi][ni][2] + bb.x, acc[mi][ni][3] + bb.y);
        }
    }
}

// ============================================================================
// Flash attention (fp32, online softmax) — unchanged validated kernel
// ============================================================================
#define ALD 68

__global__ __launch_bounds__(256) void attn_kernel()
{
    extern __shared__ float sm[];
    float* Qts = sm;
    float* Kts = sm + 64 * ALD;
    float* Vs  = sm + 2 * 64 * ALD;
    float* Ps  = sm + 3 * 64 * ALD;

    const int tid = threadIdx.x;
    const int tx = tid & 15;
    const int ty = tid >> 4;
    const int bh = blockIdx.y;
    const int q0 = blockIdx.x * 64;

    const float* Qb = g_Qh + ((size_t)bh * SEQ + q0) * DK;
    const float* Kb = g_Kh + (size_t)bh * SEQ * DK;
    const float* Vb = g_Vh + (size_t)bh * SEQ * DK;

    const int lr = tid >> 2;
    const int lc = (tid & 3) * 4;

    #pragma unroll
    for (int c = 0; c < DK; c += 16) {
        float4 t = *(const float4*)&Qb[(size_t)lr * DK + lc + c];
        Qts[(lc + c + 0) * ALD + lr] = t.x * 0.125f;
        Qts[(lc + c + 1) * ALD + lr] = t.y * 0.125f;
        Qts[(lc + c + 2) * ALD + lr] = t.z * 0.125f;
        Qts[(lc + c + 3) * ALD + lr] = t.w * 0.125f;
    }

    float m_i[4], l_i[4], acc[4][4];
    #pragma unroll
    for (int i = 0; i < 4; i++) {
        m_i[i] = -1e30f; l_i[i] = 0.0f;
        #pragma unroll
        for (int j = 0; j < 4; j++) acc[i][j] = 0.0f;
    }

    for (int k0 = 0; k0 < SEQ; k0 += 64) {
        #pragma unroll
        for (int c = 0; c < DK; c += 16) {
            float4 t = *(const float4*)&Kb[(size_t)(k0 + lr) * DK + lc + c];
            Kts[(lc + c + 0) * ALD + lr] = t.x;
            Kts[(lc + c + 1) * ALD + lr] = t.y;
            Kts[(lc + c + 2) * ALD + lr] = t.z;
            Kts[(lc + c + 3) * ALD + lr] = t.w;
            float4 u = *(const float4*)&Vb[(size_t)(k0 + lr) * DK + lc + c];
            *(float4*)&Vs[lr * ALD + lc + c] = u;
        }
        __syncthreads();

        float s[4][4] = {};
        #pragma unroll
        for (int d = 0; d < DK; d++) {
            float4 qa = *(const float4*)&Qts[d * ALD + ty * 4];
            float4 kb = *(const float4*)&Kts[d * ALD + tx * 4];
            s[0][0] += qa.x * kb.x; s[0][1] += qa.x * kb.y; s[0][2] += qa.x * kb.z; s[0][3] += qa.x * kb.w;
            s[1][0] += qa.y * kb.x; s[1][1] += qa.y * kb.y; s[1][2] += qa.y * kb.z; s[1][3] += qa.y * kb.w;
            s[2][0] += qa.z * kb.x; s[2][1] += qa.z * kb.y; s[2][2] += qa.z * kb.z; s[2][3] += qa.z * kb.w;
            s[3][0] += qa.w * kb.x; s[3][1] += qa.w * kb.y; s[3][2] += qa.w * kb.z; s[3][3] += qa.w * kb.w;
        }

        #pragma unroll
        for (int i = 0; i < 4; i++) {
            float mx = fmaxf(fmaxf(s[i][0], s[i][1]), fmaxf(s[i][2], s[i][3]));
            mx = fmaxf(mx, __shfl_xor_sync(0xffffffffu, mx, 1));
            mx = fmaxf(mx, __shfl_xor_sync(0xffffffffu, mx, 2));
            mx = fmaxf(mx, __shfl_xor_sync(0xffffffffu, mx, 4));
            mx = fmaxf(mx, __shfl_xor_sync(0xffffffffu, mx, 8));
            float mnew = fmaxf(m_i[i], mx);
            float corr = __expf(m_i[i] - mnew);
            float rs = 0.0f;
            #pragma unroll
            for (int j = 0; j < 4; j++) { s[i][j] = __expf(s[i][j] - mnew); rs += s[i][j]; }
            rs += __shfl_xor_sync(0xffffffffu, rs, 1);
            rs += __shfl_xor_sync(0xffffffffu, rs, 2);
            rs += __shfl_xor_sync(0xffffffffu, rs, 4);
            rs += __shfl_xor_sync(0xffffffffu, rs, 8);
            l_i[i] = l_i[i] * corr + rs;
            m_i[i] = mnew;
            #pragma unroll
            for (int j = 0; j < 4; j++) acc[i][j] *= corr;
            *(float4*)&Ps[(ty * 4 + i) * ALD + tx * 4] = make_float4(s[i][0], s[i][1], s[i][2], s[i][3]);
        }
        __syncthreads();

        #pragma unroll 8
        for (int kk = 0; kk < 64; kk++) {
            float4 vv = *(const float4*)&Vs[kk * ALD + tx * 4];
            float p0 = Ps[(ty * 4 + 0) * ALD + kk];
            float p1 = Ps[(ty * 4 + 1) * ALD + kk];
            float p2 = Ps[(ty * 4 + 2) * ALD + kk];
            float p3 = Ps[(ty * 4 + 3) * ALD + kk];
            acc[0][0] += p0 * vv.x; acc[0][1] += p0 * vv.y; acc[0][2] += p0 * vv.z; acc[0][3] += p0 * vv.w;
            acc[1][0] += p1 * vv.x; acc[1][1] += p1 * vv.y; acc[1][2] += p1 * vv.z; acc[1][3] += p1 * vv.w;
            acc[2][0] += p2 * vv.x; acc[2][1] += p2 * vv.y; acc[2][2] += p2 * vv.z; acc[2][3] += p2 * vv.w;
            acc[3][0] += p3 * vv.x; acc[3][1] += p3 * vv.y; acc[3][2] += p3 * vv.z; acc[3][3] += p3 * vv.w;
        }
        __syncthreads();
    }

    const int b_idx = bh >> 4;
    const int h     = bh & 15;
    #pragma unroll
    for (int i = 0; i < 4; i++) {
        float inv = 1.0f / l_i[i];
        int srow = q0 + ty * 4 + i;
        float4 o = make_float4(acc[i][0] * inv, acc[i][1] * inv, acc[i][2] * inv, acc[i][3] * inv);
        size_t base = ((size_t)b_idx * SEQ + srow) * D_MODEL + h * DK + tx * 4;
        *(float4*)&g_ctx[base] = o;
    }
}

// ============================================================================
// Launch
// ============================================================================
extern "C" void kernel_launch(void* const* d_in, const int* in_sizes, int n_in,
                              void* d_out, int out_size)
{
    const float* q  = (const float*)d_in[0];
    const float* k  = (const float*)d_in[1];
    const float* v  = (const float*)d_in[2];
    const float* Wq = (const float*)d_in[3];
    const float* bq = (const float*)d_in[4];
    const float* Wk = (const float*)d_in[5];
    const float* bk = (const float*)d_in[6];
    const float* Wv = (const float*)d_in[7];
    const float* bv = (const float*)d_in[8];
    const float* Wo = (const float*)d_in[9];
    const float* bo = (const float*)d_in[10];
    float* out = (float*)d_out;

    const int attn_smem = 4 * 64 * ALD * (int)sizeof(float);
    cudaFuncSetAttribute(attn_kernel, cudaFuncAttributeMaxDynamicSharedMemorySize, attn_smem);
    cudaFuncSetAttribute(qkv_tc_kernel, cudaFuncAttributeMaxDynamicSharedMemorySize, GEMM_SMEM);
    cudaFuncSetAttribute(out_tc_kernel, cudaFuncAttributeMaxDynamicSharedMemorySize, GEMM_SMEM);

    dim3 gqkv(D_MODEL / 128, TOKENS / 128, 3);
    qkv_tc_kernel<<<gqkv, 256, GEMM_SMEM>>>(q, k, v, Wq, bq, Wk, bk, Wv, bv);

    dim3 gattn(SEQ / 64, BATCH * NHEAD);
    attn_kernel<<<gattn, 256, attn_smem>>>();

    dim3 gout(D_MODEL / 128, TOKENS / 128);
    out_tc_kernel<<<gout, 256, GEMM_SMEM>>>(Wo, bo, out);
}

// round 4
// speedup vs baseline: 2.0383x; 1.2071x over previous
#include <cuda_runtime.h>
#include <cstdint>

#define D_MODEL 1024
#define NHEAD   16
#define DK      64
#define BATCH   2
#define SEQ     2048
#define TOKENS  (BATCH * SEQ)   // 4096

// ---------------- scratch (device globals; no allocations allowed) ----------
__device__ float g_Qh[BATCH * NHEAD * SEQ * DK];   // [B,H,S,dk]
__device__ float g_Kh[BATCH * NHEAD * SEQ * DK];
__device__ float g_Vh[BATCH * NHEAD * SEQ * DK];
__device__ float g_ctx[TOKENS * D_MODEL];          // [B,S,D] attention output

// ============================================================================
// Helpers (plain sm_80-era PTX only)
// ============================================================================
__device__ __forceinline__ uint32_t smem_u32(const void* p) {
    uint32_t a;
    asm("{ .reg .u64 t; cvta.to.shared.u64 t, %1; cvt.u32.u64 %0, t; }" : "=r"(a) : "l"(p));
    return a;
}
__device__ __forceinline__ uint32_t f2tf32(float f) {
    uint32_t u;
    asm("cvt.rna.tf32.f32 %0, %1;" : "=r"(u) : "f"(f));
    return u;
}
__device__ __forceinline__ float tf32r(float f) { return __uint_as_float(f2tf32(f)); }

__device__ __forceinline__ void cp16(uint32_t dst, const void* src) {
    asm volatile("cp.async.cg.shared.global [%0], [%1], 16;" :: "r"(dst), "l"(src));
}
#define CP_COMMIT() asm volatile("cp.async.commit_group;" ::: "memory")
#define CP_WAIT1()  asm volatile("cp.async.wait_group 1;" ::: "memory")
#define CP_WAIT0()  asm volatile("cp.async.wait_group 0;" ::: "memory")

__device__ __forceinline__ void mma_m16n8k8(float* d, const uint32_t* a, const uint32_t* b) {
    asm volatile(
        "mma.sync.aligned.m16n8k8.row.col.f32.tf32.tf32.f32 "
        "{%0,%1,%2,%3}, {%4,%5,%6,%7}, {%8,%9}, {%0,%1,%2,%3};"
        : "+f"(d[0]), "+f"(d[1]), "+f"(d[2]), "+f"(d[3])
        : "r"(a[0]), "r"(a[1]), "r"(a[2]), "r"(a[3]), "r"(b[0]), "r"(b[1]));
}

// ============================================================================
// tf32 mma.sync GEMM core (projections): acc = A[m0:+128,:1024] @ B[n0:+128,:1024]^T
// ============================================================================
#define SMEM_STRIDE 36
#define BUF_FLOATS  (128 * SMEM_STRIDE)
#define GEMM_SMEM   (4 * BUF_FLOATS * 4)

__device__ __forceinline__ void gemm_issue(
    const float* __restrict__ A, const float* __restrict__ B,
    int m0, int n0, int c, int buf, uint32_t sbase, int r0, int c4)
{
    const float* Asrc = A + (size_t)(m0 + r0) * D_MODEL + c * 32 + c4 * 4;
    const float* Bsrc = B + (size_t)(n0 + r0) * D_MODEL + c * 32 + c4 * 4;
    uint32_t dA = sbase + (uint32_t)((buf * BUF_FLOATS + r0 * SMEM_STRIDE + c4 * 4) * 4);
    uint32_t dB = dA + 2 * BUF_FLOATS * 4;
    #pragma unroll
    for (int i = 0; i < 4; i++) {
        cp16(dA + i * (32 * SMEM_STRIDE * 4), Asrc + (size_t)i * 32 * D_MODEL);
        cp16(dB + i * (32 * SMEM_STRIDE * 4), Bsrc + (size_t)i * 32 * D_MODEL);
    }
}

__device__ __forceinline__ void gemm_tf32(
    const float* __restrict__ A, const float* __restrict__ B,
    int m0, int n0, float acc[4][4][4])
{
    extern __shared__ float smf[];
    const uint32_t sbase = smem_u32(smf);
    const int tid  = threadIdx.x;
    const int lane = tid & 31;
    const int wid  = tid >> 5;
    const int warp_m = wid >> 2;
    const int warp_n = wid & 3;
    const int r0 = tid >> 3;
    const int c4 = tid & 7;

    #pragma unroll
    for (int mi = 0; mi < 4; mi++)
        #pragma unroll
        for (int ni = 0; ni < 4; ni++)
            #pragma unroll
            for (int r = 0; r < 4; r++) acc[mi][ni][r] = 0.0f;

    gemm_issue(A, B, m0, n0, 0, 0, sbase, r0, c4);
    CP_COMMIT();

    const float* pAbase = smf + (warp_m * 64 + (lane >> 2)) * SMEM_STRIDE + (lane & 3);
    const float* pBbase = smf + 2 * BUF_FLOATS + (warp_n * 32 + (lane >> 2)) * SMEM_STRIDE + (lane & 3);

    #pragma unroll 1
    for (int c = 0; c < D_MODEL / 32; c++) {
        if (c < D_MODEL / 32 - 1) {
            gemm_issue(A, B, m0, n0, c + 1, (c + 1) & 1, sbase, r0, c4);
            CP_COMMIT();
            CP_WAIT1();
        } else {
            CP_WAIT0();
        }
        __syncthreads();

        const float* pA = pAbase + (c & 1) * BUF_FLOATS;
        const float* pB = pBbase + (c & 1) * BUF_FLOATS;

        #pragma unroll
        for (int ki = 0; ki < 4; ki++) {
            uint32_t af[4][4], bf[4][2];
            #pragma unroll
            for (int mi = 0; mi < 4; mi++) {
                int base = mi * (16 * SMEM_STRIDE) + ki * 8;
                af[mi][0] = f2tf32(pA[base]);
                af[mi][1] = f2tf32(pA[base + 8 * SMEM_STRIDE]);
                af[mi][2] = f2tf32(pA[base + 4]);
                af[mi][3] = f2tf32(pA[base + 8 * SMEM_STRIDE + 4]);
            }
            #pragma unroll
            for (int ni = 0; ni < 4; ni++) {
                int base = ni * (8 * SMEM_STRIDE) + ki * 8;
                bf[ni][0] = f2tf32(pB[base]);
                bf[ni][1] = f2tf32(pB[base + 4]);
            }
            #pragma unroll
            for (int mi = 0; mi < 4; mi++)
                #pragma unroll
                for (int ni = 0; ni < 4; ni++)
                    mma_m16n8k8(acc[mi][ni], af[mi], bf[ni]);
        }
        __syncthreads();
    }
}

// ============================================================================
// QKV projection: Y = X @ W^T + b, head-major output [B,H,S,dk]
// ============================================================================
__global__ __launch_bounds__(256) void qkv_tc_kernel(
    const float* __restrict__ q,  const float* __restrict__ k,  const float* __restrict__ v,
    const float* __restrict__ Wq, const float* __restrict__ bq,
    const float* __restrict__ Wk, const float* __restrict__ bk,
    const float* __restrict__ Wv, const float* __restrict__ bv)
{
    const float* X; const float* W; const float* bias; float* Y;
    if (blockIdx.z == 0)      { X = q; W = Wq; bias = bq; Y = g_Qh; }
    else if (blockIdx.z == 1) { X = k; W = Wk; bias = bk; Y = g_Kh; }
    else                      { X = v; W = Wv; bias = bv; Y = g_Vh; }

    const int m0 = blockIdx.y * 128;
    const int n0 = blockIdx.x * 128;

    float acc[4][4][4];
    gemm_tf32(X, W, m0, n0, acc);

    const int tid  = threadIdx.x;
    const int lane = tid & 31;
    const int wid  = tid >> 5;
    const int warp_m = wid >> 2;
    const int warp_n = wid & 3;
    const int h = (n0 + warp_n * 32) >> 6;

    #pragma unroll
    for (int mi = 0; mi < 4; mi++) {
        int m_lo = m0 + warp_m * 64 + mi * 16 + (lane >> 2);
        int m_hi = m_lo + 8;
        float* row_lo = Y + (((size_t)(m_lo >> 11) * NHEAD + h) * SEQ + (m_lo & 2047)) * DK;
        float* row_hi = Y + (((size_t)(m_hi >> 11) * NHEAD + h) * SEQ + (m_hi & 2047)) * DK;
        #pragma unroll
        for (int ni = 0; ni < 4; ni++) {
            int colg = n0 + warp_n * 32 + ni * 8 + (lane & 3) * 2;
            float2 bb = *(const float2*)&bias[colg];
            int dkc = colg & 63;
            *(float2*)&row_lo[dkc] = make_float2(acc[mi][ni][0] + bb.x, acc[mi][ni][1] + bb.y);
            *(float2*)&row_hi[dkc] = make_float2(acc[mi][ni][2] + bb.x, acc[mi][ni][3] + bb.y);
        }
    }
}

// ============================================================================
// Output projection: out = ctx @ Wo^T + bo
// ============================================================================
__global__ __launch_bounds__(256) void out_tc_kernel(
    const float* __restrict__ Wo, const float* __restrict__ bo, float* __restrict__ out)
{
    const int m0 = blockIdx.y * 128;
    const int n0 = blockIdx.x * 128;

    float acc[4][4][4];
    gemm_tf32(g_ctx, Wo, m0, n0, acc);

    const int tid  = threadIdx.x;
    const int lane = tid & 31;
    const int wid  = tid >> 5;
    const int warp_m = wid >> 2;
    const int warp_n = wid & 3;

    #pragma unroll
    for (int mi = 0; mi < 4; mi++) {
        int m_lo = m0 + warp_m * 64 + mi * 16 + (lane >> 2);
        float* row_lo = out + (size_t)m_lo * D_MODEL;
        float* row_hi = row_lo + 8 * D_MODEL;
        #pragma unroll
        for (int ni = 0; ni < 4; ni++) {
            int colg = n0 + warp_n * 32 + ni * 8 + (lane & 3) * 2;
            float2 bb = *(const float2*)&bo[colg];
            *(float2*)&row_lo[colg] = make_float2(acc[mi][ni][0] + bb.x, acc[mi][ni][1] + bb.y);
            *(float2*)&row_hi[colg] = make_float2(acc[mi][ni][2] + bb.x, acc[mi][ni][3] + bb.y);
        }
    }
}

// ============================================================================
// Flash attention, tf32 mma.sync.
// Block = 128 queries of one (b,h). 8 warps x 16 query rows. Key tiles of 64.
// Smem stride 68: fragment reads bank = (4*row + k) % 32 -> conflict-free.
// P is per-warp-private (each warp computes/consumes only its own 16 rows).
// ============================================================================
#define AST 68
#define ATTN_SMEM ((128 + 64 + 64 + 128) * AST * 4)   // Q,K,Vt,P = 104448 B

__global__ __launch_bounds__(256) void attn_tc_kernel()
{
    extern __shared__ float sm[];
    float* Qs = sm;                       // [128][AST] tf32, pre-scaled by 0.125
    float* Ks = Qs + 128 * AST;           // [64][AST]  tf32, [key][dk]
    float* Vt = Ks + 64 * AST;            // [64][AST]  tf32, [dv][key]
    float* Ps = Vt + 64 * AST;            // [128][AST] tf32, [qrow][key]

    const int tid  = threadIdx.x;
    const int lane = tid & 31;
    const int wid  = tid >> 5;
    const int bh = blockIdx.y;
    const int q0 = blockIdx.x * 128;

    const float* Qb = g_Qh + ((size_t)bh * SEQ + q0) * DK;
    const float* Kb = g_Kh + (size_t)bh * SEQ * DK;
    const float* Vb = g_Vh + (size_t)bh * SEQ * DK;

    // Load Q tile (tf32-rounded, scaled by 1/sqrt(dk)=0.125)
    #pragma unroll
    for (int it = 0; it < 8; it++) {
        int idx = tid + it * 256;          // float4 index, 2048 total
        int row = idx >> 4;
        int c4  = (idx & 15) * 4;
        float4 t = *(const float4*)&Qb[(size_t)row * DK + c4];
        Qs[row * AST + c4 + 0] = tf32r(t.x * 0.125f);
        Qs[row * AST + c4 + 1] = tf32r(t.y * 0.125f);
        Qs[row * AST + c4 + 2] = tf32r(t.z * 0.125f);
        Qs[row * AST + c4 + 3] = tf32r(t.w * 0.125f);
    }

    float o[8][4];
    float m_i[2] = {-1e30f, -1e30f};
    float l_i[2] = {0.0f, 0.0f};
    #pragma unroll
    for (int ni = 0; ni < 8; ni++)
        #pragma unroll
        for (int r = 0; r < 4; r++) o[ni][r] = 0.0f;

    const uint32_t* pQ = (const uint32_t*)(Qs + (wid * 16 + (lane >> 2)) * AST + (lane & 3));
    const uint32_t* pK = (const uint32_t*)(Ks + (lane >> 2) * AST + (lane & 3));
    const uint32_t* pP = (const uint32_t*)(Ps + (wid * 16 + (lane >> 2)) * AST + (lane & 3));
    const uint32_t* pV = (const uint32_t*)(Vt + (lane >> 2) * AST + (lane & 3));
    float* wP = Ps + (wid * 16 + (lane >> 2)) * AST + (lane & 3) * 2;

    #pragma unroll 1
    for (int k0 = 0; k0 < SEQ; k0 += 64) {
        __syncthreads();   // previous tile fully consumed
        // Load K tile [key][dk] and V tile transposed [dv][key], tf32-rounded
        #pragma unroll
        for (int it = 0; it < 4; it++) {
            int idx = tid + it * 256;      // 1024 float4
            int row = idx >> 4;
            int c4  = (idx & 15) * 4;
            float4 t = *(const float4*)&Kb[(size_t)(k0 + row) * DK + c4];
            Ks[row * AST + c4 + 0] = tf32r(t.x);
            Ks[row * AST + c4 + 1] = tf32r(t.y);
            Ks[row * AST + c4 + 2] = tf32r(t.z);
            Ks[row * AST + c4 + 3] = tf32r(t.w);
            float4 u = *(const float4*)&Vb[(size_t)(k0 + row) * DK + c4];
            Vt[(c4 + 0) * AST + row] = tf32r(u.x);
            Vt[(c4 + 1) * AST + row] = tf32r(u.y);
            Vt[(c4 + 2) * AST + row] = tf32r(u.z);
            Vt[(c4 + 3) * AST + row] = tf32r(u.w);
        }
        __syncthreads();

        // S = Q K^T : warp tile 16 x 64
        float s[8][4];
        #pragma unroll
        for (int ni = 0; ni < 8; ni++)
            #pragma unroll
            for (int r = 0; r < 4; r++) s[ni][r] = 0.0f;

        #pragma unroll
        for (int ki = 0; ki < 8; ki++) {
            uint32_t aq[4];
            aq[0] = pQ[ki * 8];
            aq[1] = pQ[8 * AST + ki * 8];
            aq[2] = pQ[ki * 8 + 4];
            aq[3] = pQ[8 * AST + ki * 8 + 4];
            #pragma unroll
            for (int ni = 0; ni < 8; ni++) {
                uint32_t bk[2] = { pK[ni * 8 * AST + ki * 8], pK[ni * 8 * AST + ki * 8 + 4] };
                mma_m16n8k8(s[ni], aq, bk);
            }
        }

        // Online softmax: thread owns 2 rows (lane>>2 and +8), 16 vals each
        #pragma unroll
        for (int h = 0; h < 2; h++) {
            float mx = -1e30f;
            #pragma unroll
            for (int ni = 0; ni < 8; ni++)
                mx = fmaxf(mx, fmaxf(s[ni][2 * h], s[ni][2 * h + 1]));
            mx = fmaxf(mx, __shfl_xor_sync(0xffffffffu, mx, 1));
            mx = fmaxf(mx, __shfl_xor_sync(0xffffffffu, mx, 2));
            float mnew = fmaxf(m_i[h], mx);
            float corr = __expf(m_i[h] - mnew);
            float rs = 0.0f;
            #pragma unroll
            for (int ni = 0; ni < 8; ni++) {
                float p0 = __expf(s[ni][2 * h]     - mnew);
                float p1 = __expf(s[ni][2 * h + 1] - mnew);
                rs += p0 + p1;
                wP[h * 8 * AST + ni * 8] = tf32r(p0);
                wP[h * 8 * AST + ni * 8 + 1] = tf32r(p1);
            }
            rs += __shfl_xor_sync(0xffffffffu, rs, 1);
            rs += __shfl_xor_sync(0xffffffffu, rs, 2);
            l_i[h] = l_i[h] * corr + rs;
            m_i[h] = mnew;
            #pragma unroll
            for (int ni = 0; ni < 8; ni++) {
                o[ni][2 * h]     *= corr;
                o[ni][2 * h + 1] *= corr;
            }
        }
        __syncwarp();   // P rows are warp-private: warp-level visibility suffices

        // O += P @ V^T
        #pragma unroll
        for (int ki = 0; ki < 8; ki++) {
            uint32_t ap[4];
            ap[0] = pP[ki * 8];
            ap[1] = pP[8 * AST + ki * 8];
            ap[2] = pP[ki * 8 + 4];
            ap[3] = pP[8 * AST + ki * 8 + 4];
            #pragma unroll
            for (int ni = 0; ni < 8; ni++) {
                uint32_t bv[2] = { pV[ni * 8 * AST + ki * 8], pV[ni * 8 * AST + ki * 8 + 4] };
                mma_m16n8k8(o[ni], ap, bv);
            }
        }
        __syncwarp();   // PV reads done before next-iteration P stores
    }

    // Epilogue: normalize, write to g_ctx[B,S,D]
    const int b_idx = bh >> 4;
    const int hh    = bh & 15;
    #pragma unroll
    for (int h = 0; h < 2; h++) {
        float inv = 1.0f / l_i[h];
        int row = q0 + wid * 16 + (lane >> 2) + 8 * h;
        float* dst = g_ctx + ((size_t)b_idx * SEQ + row) * D_MODEL + hh * DK;
        #pragma unroll
        for (int ni = 0; ni < 8; ni++) {
            int col = ni * 8 + (lane & 3) * 2;
            *(float2*)&dst[col] = make_float2(o[ni][2 * h] * inv, o[ni][2 * h + 1] * inv);
        }
    }
}

// ============================================================================
// Launch
// ============================================================================
extern "C" void kernel_launch(void* const* d_in, const int* in_sizes, int n_in,
                              void* d_out, int out_size)
{
    const float* q  = (const float*)d_in[0];
    const float* k  = (const float*)d_in[1];
    const float* v  = (const float*)d_in[2];
    const float* Wq = (const float*)d_in[3];
    const float* bq = (const float*)d_in[4];
    const float* Wk = (const float*)d_in[5];
    const float* bk = (const float*)d_in[6];
    const float* Wv = (const float*)d_in[7];
    const float* bv = (const float*)d_in[8];
    const float* Wo = (const float*)d_in[9];
    const float* bo = (const float*)d_in[10];
    float* out = (float*)d_out;

    cudaFuncSetAttribute(qkv_tc_kernel,  cudaFuncAttributeMaxDynamicSharedMemorySize, GEMM_SMEM);
    cudaFuncSetAttribute(out_tc_kernel,  cudaFuncAttributeMaxDynamicSharedMemorySize, GEMM_SMEM);
    cudaFuncSetAttribute(attn_tc_kernel, cudaFuncAttributeMaxDynamicSharedMemorySize, ATTN_SMEM);

    dim3 gqkv(D_MODEL / 128, TOKENS / 128, 3);
    qkv_tc_kernel<<<gqkv, 256, GEMM_SMEM>>>(q, k, v, Wq, bq, Wk, bk, Wv, bv);

    dim3 gattn(SEQ / 128, BATCH * NHEAD);
    attn_tc_kernel<<<gattn, 256, ATTN_SMEM>>>();

    dim3 gout(D_MODEL / 128, TOKENS / 128);
    out_tc_kernel<<<gout, 256, GEMM_SMEM>>>(Wo, bo, out);
}

// round 8
// speedup vs baseline: 2.6864x; 1.3180x over previous
#include <cuda_runtime.h>
#include <cstdint>

#define D_MODEL 1024
#define NHEAD   16
#define DK      64
#define BATCH   2
#define SEQ     2048
#define TOKENS  (BATCH * SEQ)   // 4096

// ---------------- scratch (device globals; no allocations allowed) ----------
__device__ float g_Qh[BATCH * NHEAD * SEQ * DK];   // [B,H,S,dk]
__device__ float g_Kh[BATCH * NHEAD * SEQ * DK];
__device__ float g_Vh[BATCH * NHEAD * SEQ * DK];
__device__ float g_ctx[TOKENS * D_MODEL];          // [B,S,D] attention output

// ============================================================================
// Helpers (plain sm_80-era PTX only; ldmatrix is sm_75+)
// ============================================================================
__device__ __forceinline__ uint32_t smem_u32(const void* p) {
    uint32_t a;
    asm("{ .reg .u64 t; cvta.to.shared.u64 t, %1; cvt.u32.u64 %0, t; }" : "=r"(a) : "l"(p));
    return a;
}
__device__ __forceinline__ uint32_t f2tf32(float f) {
    uint32_t u;
    asm("cvt.rna.tf32.f32 %0, %1;" : "=r"(u) : "f"(f));
    return u;
}
__device__ __forceinline__ float tf32r(float f) { return __uint_as_float(f2tf32(f)); }

__device__ __forceinline__ void mma_m16n8k8(float* d, const uint32_t* a, const uint32_t* b) {
    asm volatile(
        "mma.sync.aligned.m16n8k8.row.col.f32.tf32.tf32.f32 "
        "{%0,%1,%2,%3}, {%4,%5,%6,%7}, {%8,%9}, {%0,%1,%2,%3};"
        : "+f"(d[0]), "+f"(d[1]), "+f"(d[2]), "+f"(d[3])
        : "r"(a[0]), "r"(a[1]), "r"(a[2]), "r"(a[3]), "r"(b[0]), "r"(b[1]));
}
__device__ __forceinline__ void ldsm4(uint32_t* r, uint32_t a) {
    asm volatile("ldmatrix.sync.aligned.m8n8.x4.shared.b16 {%0,%1,%2,%3}, [%4];"
                 : "=r"(r[0]), "=r"(r[1]), "=r"(r[2]), "=r"(r[3]) : "r"(a));
}

// ============================================================================
// tf32 GEMM core (projections): acc = A[m0:+128,:1024] @ B[n0:+128,:1024]^T
// BM=BN=128, BK=32, 256 threads, warp grid 2(m) x 4(n), warp tile 64x32.
// Reg-staged pipeline: LDG chunk c+2, cvt+STS chunk c+1, compute chunk c.
// All fragments via ldmatrix.x4; smem is pre-converted tf32.
// ============================================================================
#define SMEM_STRIDE 36
#define BUF_FLOATS  (128 * SMEM_STRIDE)
#define GEMM_SMEM   (4 * BUF_FLOATS * 4)   // 73728 B

__device__ __forceinline__ void gemm_tf32(
    const float* __restrict__ A, const float* __restrict__ B,
    int m0, int n0, float acc[4][4][4])
{
    extern __shared__ float smf[];
    const uint32_t sb = smem_u32(smf);
    const int tid = threadIdx.x, lane = tid & 31, wid = tid >> 5;
    const int warp_m = wid >> 2, warp_n = wid & 3;
    const int r0 = tid >> 3, c4 = (tid & 7) * 4;

    #pragma unroll
    for (int mi = 0; mi < 4; mi++)
        #pragma unroll
        for (int ni = 0; ni < 4; ni++)
            #pragma unroll
            for (int r = 0; r < 4; r++) acc[mi][ni][r] = 0.0f;

    // fragment base addresses (bytes) into buffer 0
    const int frow = (lane & 7) + ((lane >> 3) & 1) * 8;
    const int fcol = ((lane >> 4) & 1) * 4;
    const uint32_t aAddr = sb + (uint32_t)(((warp_m * 64 + frow) * SMEM_STRIDE + fcol) * 4);
    const uint32_t bAddr = sb + (uint32_t)(2 * BUF_FLOATS * 4)
                         + (uint32_t)(((warp_n * 32 + (lane & 7)) * SMEM_STRIDE + (lane >> 3) * 4) * 4);

    const float* Ap = A + (size_t)(m0 + r0) * D_MODEL + c4;
    const float* Bp = B + (size_t)(n0 + r0) * D_MODEL + c4;

    float4 ar[4], br[4];
    // prologue: chunk0 -> regs -> buf0 ; chunk1 -> regs
    #pragma unroll
    for (int i = 0; i < 4; i++) {
        ar[i] = *(const float4*)(Ap + (size_t)i * 32 * D_MODEL);
        br[i] = *(const float4*)(Bp + (size_t)i * 32 * D_MODEL);
    }
    #pragma unroll
    for (int i = 0; i < 4; i++) {
        *(float4*)(smf + (r0 + 32 * i) * SMEM_STRIDE + c4) =
            make_float4(tf32r(ar[i].x), tf32r(ar[i].y), tf32r(ar[i].z), tf32r(ar[i].w));
        *(float4*)(smf + 2 * BUF_FLOATS + (r0 + 32 * i) * SMEM_STRIDE + c4) =
            make_float4(tf32r(br[i].x), tf32r(br[i].y), tf32r(br[i].z), tf32r(br[i].w));
    }
    #pragma unroll
    for (int i = 0; i < 4; i++) {
        ar[i] = *(const float4*)(Ap + 32 + (size_t)i * 32 * D_MODEL);
        br[i] = *(const float4*)(Bp + 32 + (size_t)i * 32 * D_MODEL);
    }
    __syncthreads();

    #pragma unroll 1
    for (int c = 0; c < 32; c++) {
        if (c + 1 < 32) {
            float* dA = smf + ((c + 1) & 1) * BUF_FLOATS;
            float* dB = smf + 2 * BUF_FLOATS + ((c + 1) & 1) * BUF_FLOATS;
            #pragma unroll
            for (int i = 0; i < 4; i++) {
                *(float4*)(dA + (r0 + 32 * i) * SMEM_STRIDE + c4) =
                    make_float4(tf32r(ar[i].x), tf32r(ar[i].y), tf32r(ar[i].z), tf32r(ar[i].w));
                *(float4*)(dB + (r0 + 32 * i) * SMEM_STRIDE + c4) =
                    make_float4(tf32r(br[i].x), tf32r(br[i].y), tf32r(br[i].z), tf32r(br[i].w));
            }
            if (c + 2 < 32) {
                #pragma unroll
                for (int i = 0; i < 4; i++) {
                    ar[i] = *(const float4*)(Ap + (c + 2) * 32 + (size_t)i * 32 * D_MODEL);
                    br[i] = *(const float4*)(Bp + (c + 2) * 32 + (size_t)i * 32 * D_MODEL);
                }
            }
        }
        const uint32_t ab = aAddr + (uint32_t)((c & 1) * BUF_FLOATS * 4);
        const uint32_t bb = bAddr + (uint32_t)((c & 1) * BUF_FLOATS * 4);

        #pragma unroll
        for (int kp = 0; kp < 2; kp++) {
            uint32_t bfr[4][4], af0[4][4], af1[4][4];
            #pragma unroll
            for (int ni = 0; ni < 4; ni++)
                ldsm4(bfr[ni], bb + (uint32_t)((ni * 8 * SMEM_STRIDE + kp * 16) * 4));
            #pragma unroll
            for (int mi = 0; mi < 4; mi++) {
                ldsm4(af0[mi], ab + (uint32_t)((mi * 16 * SMEM_STRIDE + kp * 16) * 4));
                ldsm4(af1[mi], ab + (uint32_t)((mi * 16 * SMEM_STRIDE + kp * 16 + 8) * 4));
            }
            #pragma unroll
            for (int mi = 0; mi < 4; mi++)
                #pragma unroll
                for (int ni = 0; ni < 4; ni++) {
                    mma_m16n8k8(acc[mi][ni], af0[mi], bfr[ni]);
                    mma_m16n8k8(acc[mi][ni], af1[mi], bfr[ni] + 2);
                }
        }
        __syncthreads();
    }
}

// ============================================================================
// QKV projection: Y = X @ W^T + b, head-major output [B,H,S,dk]
// ============================================================================
__global__ __launch_bounds__(256) void qkv_tc_kernel(
    const float* __restrict__ q,  const float* __restrict__ k,  const float* __restrict__ v,
    const float* __restrict__ Wq, const float* __restrict__ bq,
    const float* __restrict__ Wk, const float* __restrict__ bk,
    const float* __restrict__ Wv, const float* __restrict__ bv)
{
    const float* X; const float* W; const float* bias; float* Y;
    if (blockIdx.z == 0)      { X = q; W = Wq; bias = bq; Y = g_Qh; }
    else if (blockIdx.z == 1) { X = k; W = Wk; bias = bk; Y = g_Kh; }
    else                      { X = v; W = Wv; bias = bv; Y = g_Vh; }

    const int m0 = blockIdx.y * 128;
    const int n0 = blockIdx.x * 128;

    float acc[4][4][4];
    gemm_tf32(X, W, m0, n0, acc);

    const int tid = threadIdx.x, lane = tid & 31, wid = tid >> 5;
    const int warp_m = wid >> 2, warp_n = wid & 3;
    const int h = (n0 + warp_n * 32) >> 6;

    #pragma unroll
    for (int mi = 0; mi < 4; mi++) {
        int m_lo = m0 + warp_m * 64 + mi * 16 + (lane >> 2);
        int m_hi = m_lo + 8;
        float* row_lo = Y + (((size_t)(m_lo >> 11) * NHEAD + h) * SEQ + (m_lo & 2047)) * DK;
        float* row_hi = Y + (((size_t)(m_hi >> 11) * NHEAD + h) * SEQ + (m_hi & 2047)) * DK;
        #pragma unroll
        for (int ni = 0; ni < 4; ni++) {
            int colg = n0 + warp_n * 32 + ni * 8 + (lane & 3) * 2;
            float2 bb = *(const float2*)&bias[colg];
            int dkc = colg & 63;
            *(float2*)&row_lo[dkc] = make_float2(acc[mi][ni][0] + bb.x, acc[mi][ni][1] + bb.y);
            *(float2*)&row_hi[dkc] = make_float2(acc[mi][ni][2] + bb.x, acc[mi][ni][3] + bb.y);
        }
    }
}

// ============================================================================
// Output projection: out = ctx @ Wo^T + bo
// ============================================================================
__global__ __launch_bounds__(256) void out_tc_kernel(
    const float* __restrict__ Wo, const float* __restrict__ bo, float* __restrict__ out)
{
    const int m0 = blockIdx.y * 128;
    const int n0 = blockIdx.x * 128;

    float acc[4][4][4];
    gemm_tf32(g_ctx, Wo, m0, n0, acc);

    const int tid = threadIdx.x, lane = tid & 31, wid = tid >> 5;
    const int warp_m = wid >> 2, warp_n = wid & 3;

    #pragma unroll
    for (int mi = 0; mi < 4; mi++) {
        int m_lo = m0 + warp_m * 64 + mi * 16 + (lane >> 2);
        float* row_lo = out + (size_t)m_lo * D_MODEL;
        float* row_hi = row_lo + 8 * D_MODEL;
        #pragma unroll
        for (int ni = 0; ni < 4; ni++) {
            int colg = n0 + warp_n * 32 + ni * 8 + (lane & 3) * 2;
            float2 bb = *(const float2*)&bo[colg];
            *(float2*)&row_lo[colg] = make_float2(acc[mi][ni][0] + bb.x, acc[mi][ni][1] + bb.y);
            *(float2*)&row_hi[colg] = make_float2(acc[mi][ni][2] + bb.x, acc[mi][ni][3] + bb.y);
        }
    }
}

// ============================================================================
// Flash attention, tf32 mma.sync + ldmatrix.
// Block = 128 queries of one (b,h). 8 warps x 16 q-rows. Key tiles of 64.
// Q fragments in registers; Ps smem aliases the dead Q staging region.
// KV staged in registers one tile ahead. exp in log2 domain (MUFU.EX2).
// ============================================================================
#define AST 68
#define ATTN_SMEM ((128 + 64 + 64) * AST * 4)   // 69632 B

__global__ __launch_bounds__(256) void attn_tc_kernel()
{
    extern __shared__ float sm[];
    float* Ps = sm;                  // [128][AST] — Q staging, then P tiles
    float* Ks = sm + 128 * AST;      // [64][AST]  tf32 [key][dk]
    float* Vt = Ks + 64 * AST;       // [64][AST]  tf32 [dv][key]

    const int tid = threadIdx.x, lane = tid & 31, wid = tid >> 5;
    const int bh = blockIdx.y, q0 = blockIdx.x * 128;
    const uint32_t sb = smem_u32(sm);

    const float* Qb = g_Qh + ((size_t)bh * SEQ + q0) * DK;
    const float* Kb = g_Kh + (size_t)bh * SEQ * DK;
    const float* Vb = g_Vh + (size_t)bh * SEQ * DK;

    // ---- Q -> smem, scaled by (1/sqrt(dk)) * log2(e), tf32-rounded
    const float QSCALE = 0.18033688011112042f;   // 0.125 * log2(e)
    #pragma unroll
    for (int it = 0; it < 8; it++) {
        int idx = tid + it * 256;
        int row = idx >> 4, c4 = (idx & 15) * 4;
        float4 t = *(const float4*)&Qb[(size_t)row * DK + c4];
        *(float4*)&Ps[row * AST + c4] =
            make_float4(tf32r(t.x * QSCALE), tf32r(t.y * QSCALE), tf32r(t.z * QSCALE), tf32r(t.w * QSCALE));
    }

    // ---- stage KV tile 0 into registers (bank-conflict-free store mappings)
    const int w4 = wid & 3, wh = wid >> 2;
    float4 kr[4], vr[4];
    #pragma unroll
    for (int i = 0; i < 4; i++) {
        int krw = w4 * 8 + (lane & 7) + 32 * (i & 1);
        int ks  = (lane >> 3) + 4 * wh + 8 * (i >> 1);
        kr[i] = *(const float4*)&Kb[(size_t)krw * DK + ks * 4];
        int vrw = w4 * 16 + (lane & 15);
        int vs  = (lane >> 4) + 2 * wh + 4 * i;
        vr[i] = *(const float4*)&Vb[(size_t)vrw * DK + vs * 4];
    }
    __syncthreads();

    // ---- Q fragments -> registers (loop-invariant)
    const int frow = (lane & 7) + ((lane >> 3) & 1) * 8;
    const int fcol = ((lane >> 4) & 1) * 4;
    const uint32_t qAddr = sb + (uint32_t)(((wid * 16 + frow) * AST + fcol) * 4);
    uint32_t qf[8][4];
    #pragma unroll
    for (int ki = 0; ki < 8; ki++) ldsm4(qf[ki], qAddr + ki * 32);

    const uint32_t kAddr = sb + (uint32_t)((128 * AST + (lane & 7) * AST + (lane >> 3) * 4) * 4);
    const uint32_t vAddr = kAddr + (uint32_t)(64 * AST * 4);

    float o[8][4];
    float m_i[2] = {-1e30f, -1e30f};
    float l_i[2] = {0.0f, 0.0f};
    #pragma unroll
    for (int ni = 0; ni < 8; ni++)
        #pragma unroll
        for (int r = 0; r < 4; r++) o[ni][r] = 0.0f;

    float* wP = Ps + (wid * 16 + (lane >> 2)) * AST + (lane & 3) * 2;

    #pragma unroll 1
    for (int t = 0; t < 32; t++) {
        // store staged KV (tf32), prefetch next tile
        #pragma unroll
        for (int i = 0; i < 4; i++) {
            int krw = w4 * 8 + (lane & 7) + 32 * (i & 1);
            int ks4 = ((lane >> 3) + 4 * wh + 8 * (i >> 1)) * 4;
            *(float4*)&Ks[krw * AST + ks4] =
                make_float4(tf32r(kr[i].x), tf32r(kr[i].y), tf32r(kr[i].z), tf32r(kr[i].w));
            int vrw = w4 * 16 + (lane & 15);
            int vs4 = ((lane >> 4) + 2 * wh + 4 * i) * 4;
            Vt[(vs4 + 0) * AST + vrw] = tf32r(vr[i].x);
            Vt[(vs4 + 1) * AST + vrw] = tf32r(vr[i].y);
            Vt[(vs4 + 2) * AST + vrw] = tf32r(vr[i].z);
            Vt[(vs4 + 3) * AST + vrw] = tf32r(vr[i].w);
        }
        if (t + 1 < 32) {
            const float* Kn = Kb + (size_t)(t + 1) * 64 * DK;
            const float* Vn = Vb + (size_t)(t + 1) * 64 * DK;
            #pragma unroll
            for (int i = 0; i < 4; i++) {
                int krw = w4 * 8 + (lane & 7) + 32 * (i & 1);
                int ks  = (lane >> 3) + 4 * wh + 8 * (i >> 1);
                kr[i] = *(const float4*)&Kn[(size_t)krw * DK + ks * 4];
                int vrw = w4 * 16 + (lane & 15);
                int vs  = (lane >> 4) + 2 * wh + 4 * i;
                vr[i] = *(const float4*)&Vn[(size_t)vrw * DK + vs * 4];
            }
        }
        __syncthreads();

        // ---- S = Q K^T (warp tile 16 x 64)
        float s[8][4];
        #pragma unroll
        for (int ni = 0; ni < 8; ni++)
            #pragma unroll
            for (int r = 0; r < 4; r++) s[ni][r] = 0.0f;

        #pragma unroll
        for (int ni = 0; ni < 8; ni++) {
            #pragma unroll
            for (int kp = 0; kp < 4; kp++) {
                uint32_t b4[4];
                ldsm4(b4, kAddr + (uint32_t)((ni * 8 * AST + kp * 16) * 4));
                mma_m16n8k8(s[ni], qf[2 * kp],     b4);
                mma_m16n8k8(s[ni], qf[2 * kp + 1], b4 + 2);
            }
        }

        // ---- online softmax (log2 domain)
        #pragma unroll
        for (int h = 0; h < 2; h++) {
            float mx = -1e30f;
            #pragma unroll
            for (int ni = 0; ni < 8; ni++)
                mx = fmaxf(mx, fmaxf(s[ni][2 * h], s[ni][2 * h + 1]));
            mx = fmaxf(mx, __shfl_xor_sync(0xffffffffu, mx, 1));
            mx = fmaxf(mx, __shfl_xor_sync(0xffffffffu, mx, 2));
            float mnew = fmaxf(m_i[h], mx);
            float corr = exp2f(m_i[h] - mnew);
            float rs = 0.0f;
            #pragma unroll
            for (int ni = 0; ni < 8; ni++) {
                float p0 = exp2f(s[ni][2 * h]     - mnew);
                float p1 = exp2f(s[ni][2 * h + 1] - mnew);
                rs += p0 + p1;
                *(float2*)&wP[h * 8 * AST + ni * 8] = make_float2(tf32r(p0), tf32r(p1));
            }
            rs += __shfl_xor_sync(0xffffffffu, rs, 1);
            rs += __shfl_xor_sync(0xffffffffu, rs, 2);
            l_i[h] = l_i[h] * corr + rs;
            m_i[h] = mnew;
            #pragma unroll
            for (int ni = 0; ni < 8; ni++) {
                o[ni][2 * h]     *= corr;
                o[ni][2 * h + 1] *= corr;
            }
        }
        __syncwarp();   // P rows are warp-private

        // ---- O += P @ V^T
        uint32_t pf[8][4];
        #pragma unroll
        for (int ki = 0; ki < 8; ki++) ldsm4(pf[ki], qAddr + ki * 32);
        #pragma unroll
        for (int ni = 0; ni < 8; ni++) {
            #pragma unroll
            for (int kp = 0; kp < 4; kp++) {
                uint32_t b4[4];
                ldsm4(b4, vAddr + (uint32_t)((ni * 8 * AST + kp * 16) * 4));
                mma_m16n8k8(o[ni], pf[2 * kp],     b4);
                mma_m16n8k8(o[ni], pf[2 * kp + 1], b4 + 2);
            }
        }
        __syncthreads();
    }

    // ---- epilogue: normalize, write to g_ctx[B,S,D]
    const int b_idx = bh >> 4;
    const int hh    = bh & 15;
    #pragma unroll
    for (int h = 0; h < 2; h++) {
        float inv = 1.0f / l_i[h];
        int row = q0 + wid * 16 + (lane >> 2) + 8 * h;
        float* dst = g_ctx + ((size_t)b_idx * SEQ + row) * D_MODEL + hh * DK;
        #pragma unroll
        for (int ni = 0; ni < 8; ni++) {
            int col = ni * 8 + (lane & 3) * 2;
            *(float2*)&dst[col] = make_float2(o[ni][2 * h] * inv, o[ni][2 * h + 1] * inv);
        }
    }
}

// ============================================================================
// Launch
// ============================================================================
extern "C" void kernel_launch(void* const* d_in, const int* in_sizes, int n_in,
                              void* d_out, int out_size)
{
    const float* q  = (const float*)d_in[0];
    const float* k  = (const float*)d_in[1];
    const float* v  = (const float*)d_in[2];
    const float* Wq = (const float*)d_in[3];
    const float* bq = (const float*)d_in[4];
    const float* Wk = (const float*)d_in[5];
    const float* bk = (const float*)d_in[6];
    const float* Wv = (const float*)d_in[7];
    const float* bv = (const float*)d_in[8];
    const float* Wo = (const float*)d_in[9];
    const float* bo = (const float*)d_in[10];
    float* out = (float*)d_out;

    cudaFuncSetAttribute(qkv_tc_kernel,  cudaFuncAttributeMaxDynamicSharedMemorySize, GEMM_SMEM);
    cudaFuncSetAttribute(out_tc_kernel,  cudaFuncAttributeMaxDynamicSharedMemorySize, GEMM_SMEM);
    cudaFuncSetAttribute(attn_tc_kernel, cudaFuncAttributeMaxDynamicSharedMemorySize, ATTN_SMEM);

    dim3 gqkv(D_MODEL / 128, TOKENS / 128, 3);
    qkv_tc_kernel<<<gqkv, 256, GEMM_SMEM>>>(q, k, v, Wq, bq, Wk, bk, Wv, bv);

    dim3 gattn(SEQ / 128, BATCH * NHEAD);
    attn_tc_kernel<<<gattn, 256, ATTN_SMEM>>>();

    dim3 gout(D_MODEL / 128, TOKENS / 128);
    out_tc_kernel<<<gout, 256, GEMM_SMEM>>>(Wo, bo, out);
}

// round 9
// speedup vs baseline: 3.3242x; 1.2374x over previous
#include <cuda_runtime.h>
#include <cstdint>

#define D_MODEL 1024
#define NHEAD   16
#define DK      64
#define BATCH   2
#define SEQ     2048
#define TOKENS  (BATCH * SEQ)   // 4096
#define NX4     (TOKENS * D_MODEL / 4)
#define NW4     (D_MODEL * D_MODEL / 4)

// ---------------- scratch (device globals; no allocations allowed) ----------
__device__ float g_Qh[BATCH * NHEAD * SEQ * DK];   // [B,H,S,dk] tf32-valued
__device__ float g_Kh[BATCH * NHEAD * SEQ * DK];
__device__ float g_Vh[BATCH * NHEAD * SEQ * DK];
__device__ float g_ctx[TOKENS * D_MODEL];          // [B,S,D] tf32-valued
__device__ float g_X32[3 * TOKENS * D_MODEL];      // q,k,v tf32-rounded
__device__ float g_W32[4 * D_MODEL * D_MODEL];     // Wq,Wk,Wv,Wo tf32-rounded

// ============================================================================
// Helpers (plain sm_80-era PTX only)
// ============================================================================
__device__ __forceinline__ uint32_t smem_u32(const void* p) {
    uint32_t a;
    asm("{ .reg .u64 t; cvta.to.shared.u64 t, %1; cvt.u32.u64 %0, t; }" : "=r"(a) : "l"(p));
    return a;
}
__device__ __forceinline__ uint32_t f2tf32(float f) {
    uint32_t u;
    asm("cvt.rna.tf32.f32 %0, %1;" : "=r"(u) : "f"(f));
    return u;
}
__device__ __forceinline__ float tf32r(float f) { return __uint_as_float(f2tf32(f)); }

__device__ __forceinline__ void cp16(uint32_t dst, const void* src) {
    asm volatile("cp.async.cg.shared.global [%0], [%1], 16;" :: "r"(dst), "l"(src));
}
#define CP_COMMIT() asm volatile("cp.async.commit_group;" ::: "memory")
#define CP_WAIT0()  asm volatile("cp.async.wait_group 0;" ::: "memory")

__device__ __forceinline__ void mma_m16n8k8(float* d, const uint32_t* a, const uint32_t* b) {
    asm volatile(
        "mma.sync.aligned.m16n8k8.row.col.f32.tf32.tf32.f32 "
        "{%0,%1,%2,%3}, {%4,%5,%6,%7}, {%8,%9}, {%0,%1,%2,%3};"
        : "+f"(d[0]), "+f"(d[1]), "+f"(d[2]), "+f"(d[3])
        : "r"(a[0]), "r"(a[1]), "r"(a[2]), "r"(a[3]), "r"(b[0]), "r"(b[1]));
}
__device__ __forceinline__ void ldsm4(uint32_t* r, uint32_t a) {
    asm volatile("ldmatrix.sync.aligned.m8n8.x4.shared.b16 {%0,%1,%2,%3}, [%4];"
                 : "=r"(r[0]), "=r"(r[1]), "=r"(r[2]), "=r"(r[3]) : "r"(a));
}

// ============================================================================
// One-shot tf32 rounding of all GEMM inputs
// ============================================================================
__global__ __launch_bounds__(256) void cvt_tf32_kernel(
    const float* __restrict__ q,  const float* __restrict__ k,  const float* __restrict__ v,
    const float* __restrict__ Wq, const float* __restrict__ Wk,
    const float* __restrict__ Wv, const float* __restrict__ Wo)
{
    const int a = blockIdx.y;
    const float4* src; float4* dst; int n4;
    if (a < 3) {
        src = (const float4*)(a == 0 ? q : a == 1 ? k : v);
        dst = (float4*)(g_X32 + (size_t)a * TOKENS * D_MODEL);
        n4 = NX4;
    } else {
        src = (const float4*)(a == 3 ? Wq : a == 4 ? Wk : a == 5 ? Wv : Wo);
        dst = (float4*)(g_W32 + (size_t)(a - 3) * D_MODEL * D_MODEL);
        n4 = NW4;
    }
    for (int i = blockIdx.x * blockDim.x + threadIdx.x; i < n4; i += gridDim.x * blockDim.x) {
        float4 t = src[i];
        dst[i] = make_float4(tf32r(t.x), tf32r(t.y), tf32r(t.z), tf32r(t.w));
    }
}

// ============================================================================
// tf32 GEMM core: acc = A[m0:+128,:1024] @ B[n0:+128,:1024]^T
// A,B already tf32-valued in gmem. cp.async double buffer, 1 sync per chunk.
// BM=BN=128, BK=32, 256 threads, warp grid 2(m) x 4(n), warp tile 64x32.
// ============================================================================
#define SMEM_STRIDE 36
#define BUF_FLOATS  (128 * SMEM_STRIDE)
#define GEMM_SMEM   (4 * BUF_FLOATS * 4)   // 73728 B

__device__ __forceinline__ void gemm_issue(
    const float* __restrict__ A, const float* __restrict__ B,
    int m0, int n0, int c, int buf, uint32_t sb, int r0, int c4)
{
    const float* Ap = A + (size_t)(m0 + r0) * D_MODEL + c * 32 + c4;
    const float* Bp = B + (size_t)(n0 + r0) * D_MODEL + c * 32 + c4;
    uint32_t dA = sb + (uint32_t)((buf * BUF_FLOATS + r0 * SMEM_STRIDE + c4) * 4);
    uint32_t dB = dA + 2 * BUF_FLOATS * 4;
    #pragma unroll
    for (int i = 0; i < 4; i++) {
        cp16(dA + i * (32 * SMEM_STRIDE * 4), Ap + (size_t)i * 32 * D_MODEL);
        cp16(dB + i * (32 * SMEM_STRIDE * 4), Bp + (size_t)i * 32 * D_MODEL);
    }
}

__device__ __forceinline__ void gemm_cp(
    const float* __restrict__ A, const float* __restrict__ B,
    int m0, int n0, float acc[4][4][4])
{
    extern __shared__ float smf[];
    const uint32_t sb = smem_u32(smf);
    const int tid = threadIdx.x, lane = tid & 31, wid = tid >> 5;
    const int warp_m = wid >> 2, warp_n = wid & 3;
    const int r0 = tid >> 3, c4 = (tid & 7) * 4;

    #pragma unroll
    for (int mi = 0; mi < 4; mi++)
        #pragma unroll
        for (int ni = 0; ni < 4; ni++)
            #pragma unroll
            for (int r = 0; r < 4; r++) acc[mi][ni][r] = 0.0f;

    const int frow = (lane & 7) + ((lane >> 3) & 1) * 8;
    const int fcol = ((lane >> 4) & 1) * 4;
    const uint32_t aAddr = sb + (uint32_t)(((warp_m * 64 + frow) * SMEM_STRIDE + fcol) * 4);
    const uint32_t bAddr = sb + (uint32_t)(2 * BUF_FLOATS * 4)
                         + (uint32_t)(((warp_n * 32 + (lane & 7)) * SMEM_STRIDE + (lane >> 3) * 4) * 4);

    gemm_issue(A, B, m0, n0, 0, 0, sb, r0, c4);
    CP_COMMIT();

    #pragma unroll 1
    for (int c = 0; c < 32; c++) {
        CP_WAIT0();
        __syncthreads();                       // chunk c resident; all reads of buf (c+1)&1 done
        if (c + 1 < 32) {
            gemm_issue(A, B, m0, n0, c + 1, (c + 1) & 1, sb, r0, c4);
            CP_COMMIT();
        }
        const uint32_t ab = aAddr + (uint32_t)((c & 1) * BUF_FLOATS * 4);
        const uint32_t bb = bAddr + (uint32_t)((c & 1) * BUF_FLOATS * 4);

        #pragma unroll
        for (int kp = 0; kp < 2; kp++) {
            uint32_t bfr[4][4], af0[4][4], af1[4][4];
            #pragma unroll
            for (int ni = 0; ni < 4; ni++)
                ldsm4(bfr[ni], bb + (uint32_t)((ni * 8 * SMEM_STRIDE + kp * 16) * 4));
            #pragma unroll
            for (int mi = 0; mi < 4; mi++) {
                ldsm4(af0[mi], ab + (uint32_t)((mi * 16 * SMEM_STRIDE + kp * 16) * 4));
                ldsm4(af1[mi], ab + (uint32_t)((mi * 16 * SMEM_STRIDE + kp * 16 + 8) * 4));
            }
            #pragma unroll
            for (int mi = 0; mi < 4; mi++)
                #pragma unroll
                for (int ni = 0; ni < 4; ni++) {
                    mma_m16n8k8(acc[mi][ni], af0[mi], bfr[ni]);
                    mma_m16n8k8(acc[mi][ni], af1[mi], bfr[ni] + 2);
                }
        }
    }
}

// ============================================================================
// QKV projection: Y = X @ W^T + b, head-major tf32-rounded output [B,H,S,dk]
// ============================================================================
__global__ __launch_bounds__(256, 2) void qkv_tc_kernel(
    const float* __restrict__ bq, const float* __restrict__ bk, const float* __restrict__ bv)
{
    const int z = blockIdx.z;
    const float* A = g_X32 + (size_t)z * TOKENS * D_MODEL;
    const float* B = g_W32 + (size_t)z * D_MODEL * D_MODEL;
    const float* bias = (z == 0) ? bq : (z == 1) ? bk : bv;
    float* Y = (z == 0) ? g_Qh : (z == 1) ? g_Kh : g_Vh;

    const int m0 = blockIdx.y * 128;
    const int n0 = blockIdx.x * 128;

    float acc[4][4][4];
    gemm_cp(A, B, m0, n0, acc);

    const int tid = threadIdx.x, lane = tid & 31, wid = tid >> 5;
    const int warp_m = wid >> 2, warp_n = wid & 3;
    const int h = (n0 + warp_n * 32) >> 6;

    #pragma unroll
    for (int mi = 0; mi < 4; mi++) {
        int m_lo = m0 + warp_m * 64 + mi * 16 + (lane >> 2);
        int m_hi = m_lo + 8;
        float* row_lo = Y + (((size_t)(m_lo >> 11) * NHEAD + h) * SEQ + (m_lo & 2047)) * DK;
        float* row_hi = Y + (((size_t)(m_hi >> 11) * NHEAD + h) * SEQ + (m_hi & 2047)) * DK;
        #pragma unroll
        for (int ni = 0; ni < 4; ni++) {
            int colg = n0 + warp_n * 32 + ni * 8 + (lane & 3) * 2;
            float2 bb = *(const float2*)&bias[colg];
            int dkc = colg & 63;
            *(float2*)&row_lo[dkc] = make_float2(tf32r(acc[mi][ni][0] + bb.x), tf32r(acc[mi][ni][1] + bb.y));
            *(float2*)&row_hi[dkc] = make_float2(tf32r(acc[mi][ni][2] + bb.x), tf32r(acc[mi][ni][3] + bb.y));
        }
    }
}

// ============================================================================
// Output projection: out = ctx @ Wo^T + bo  (final output: full fp32, no rounding)
// ============================================================================
__global__ __launch_bounds__(256, 2) void out_tc_kernel(
    const float* __restrict__ bo, float* __restrict__ out)
{
    const int m0 = blockIdx.y * 128;
    const int n0 = blockIdx.x * 128;

    float acc[4][4][4];
    gemm_cp(g_ctx, g_W32 + (size_t)3 * D_MODEL * D_MODEL, m0, n0, acc);

    const int tid = threadIdx.x, lane = tid & 31, wid = tid >> 5;
    const int warp_m = wid >> 2, warp_n = wid & 3;

    #pragma unroll
    for (int mi = 0; mi < 4; mi++) {
        int m_lo = m0 + warp_m * 64 + mi * 16 + (lane >> 2);
        float* row_lo = out + (size_t)m_lo * D_MODEL;
        float* row_hi = row_lo + 8 * D_MODEL;
        #pragma unroll
        for (int ni = 0; ni < 4; ni++) {
            int colg = n0 + warp_n * 32 + ni * 8 + (lane & 3) * 2;
            float2 bb = *(const float2*)&bo[colg];
            *(float2*)&row_lo[colg] = make_float2(acc[mi][ni][0] + bb.x, acc[mi][ni][1] + bb.y);
            *(float2*)&row_hi[colg] = make_float2(acc[mi][ni][2] + bb.x, acc[mi][ni][3] + bb.y);
        }
    }
}

// ============================================================================
// Flash attention, tf32 mma.sync + ldmatrix.
// Block = 128 queries of one (b,h). 8 warps x 16 q-rows. Key tiles of 64.
// K arrives via cp.async (double-buffered, zero STS/cvt). V reg->smem transpose.
// Q fragments in registers; P aliases the dead Q staging region.
// ============================================================================
#define AST 68
#define ATTN_SMEM ((128 + 128 + 128) * AST * 4)   // P/Q, K x2, Vt x2 = 104448 B

__global__ __launch_bounds__(256, 2) void attn_tc_kernel()
{
    extern __shared__ float sm[];
    float* Ps = sm;                  // [128][AST] — Q staging, then P tiles
    float* Ks = sm + 128 * AST;      // 2 x [64][AST]  [key][dk]
    float* Vt = Ks + 128 * AST;      // 2 x [64][AST]  [dv][key]

    const int tid = threadIdx.x, lane = tid & 31, wid = tid >> 5;
    const int bh = blockIdx.y, q0 = blockIdx.x * 128;
    const uint32_t sb = smem_u32(sm);

    const float* Qb = g_Qh + ((size_t)bh * SEQ + q0) * DK;
    const float* Kb = g_Kh + (size_t)bh * SEQ * DK;
    const float* Vb = g_Vh + (size_t)bh * SEQ * DK;

    // ---- Q -> smem, scaled by (1/sqrt(dk)) * log2(e)
    const float QSCALE = 0.18033688011112042f;
    #pragma unroll
    for (int it = 0; it < 8; it++) {
        int idx = tid + it * 256;
        int row = idx >> 4, c4 = (idx & 15) * 4;
        float4 t = *(const float4*)&Qb[(size_t)row * DK + c4];
        *(float4*)&Ps[row * AST + c4] =
            make_float4(tf32r(t.x * QSCALE), tf32r(t.y * QSCALE), tf32r(t.z * QSCALE), tf32r(t.w * QSCALE));
    }

    // ---- issue K tile 0 via cp.async
    {
        const int row = tid >> 2, c4 = (tid & 3) * 16;   // 256 thr x 4 cp16 = 64x64
        uint32_t dst = sb + (uint32_t)((128 * AST + row * AST) * 4) + c4 * 4;
        const float* src = Kb + (size_t)row * DK + c4;
        #pragma unroll
        for (int i = 0; i < 4; i++) cp16(dst + i * 16, src + i * 4);
        CP_COMMIT();
    }
    __syncthreads();

    // ---- Q fragments -> registers (loop-invariant)
    const int frow = (lane & 7) + ((lane >> 3) & 1) * 8;
    const int fcol = ((lane >> 4) & 1) * 4;
    const uint32_t qAddr = sb + (uint32_t)(((wid * 16 + frow) * AST + fcol) * 4);
    uint32_t qf[8][4];
    #pragma unroll
    for (int ki = 0; ki < 8; ki++) ldsm4(qf[ki], qAddr + ki * 32);

    const uint32_t kAddr = sb + (uint32_t)((128 * AST + (lane & 7) * AST + (lane >> 3) * 4) * 4);
    const uint32_t vAddr = sb + (uint32_t)((256 * AST + (lane & 7) * AST + (lane >> 3) * 4) * 4);

    const int w4 = wid & 3, wh = wid >> 2;
    const int krow = tid >> 2, kc4 = (tid & 3) * 16;

    float o[8][4];
    float m_i[2] = {-1e30f, -1e30f};
    float l_i[2] = {0.0f, 0.0f};
    #pragma unroll
    for (int ni = 0; ni < 8; ni++)
        #pragma unroll
        for (int r = 0; r < 4; r++) o[ni][r] = 0.0f;

    float* wP = Ps + (wid * 16 + (lane >> 2)) * AST + (lane & 3) * 2;

    #pragma unroll 1
    for (int t = 0; t < 32; t++) {
        CP_WAIT0();
        __syncthreads();    // K(t) resident; all warps done with PV(t-1) and QK(t-1)

        // V(t) -> regs (latency hidden under QK below)
        float4 vr[4];
        #pragma unroll
        for (int i = 0; i < 4; i++) {
            int vrw = w4 * 16 + (lane & 15);
            int vs  = (lane >> 4) + 2 * wh + 4 * i;
            vr[i] = *(const float4*)&Vb[(size_t)(t * 64 + vrw) * DK + vs * 4];
        }
        // issue K(t+1)
        if (t + 1 < 32) {
            uint32_t dst = sb + (uint32_t)((128 * AST + ((t + 1) & 1) * 64 * AST + krow * AST) * 4) + kc4 * 4;
            const float* src = Kb + (size_t)((t + 1) * 64 + krow) * DK + kc4;
            #pragma unroll
            for (int i = 0; i < 4; i++) cp16(dst + i * 16, src + i * 4);
            CP_COMMIT();
        }

        // ---- S = Q K^T (warp tile 16 x 64)
        const uint32_t kb = kAddr + (uint32_t)((t & 1) * 64 * AST * 4);
        float s[8][4];
        #pragma unroll
        for (int ni = 0; ni < 8; ni++)
            #pragma unroll
            for (int r = 0; r < 4; r++) s[ni][r] = 0.0f;

        #pragma unroll
        for (int ni = 0; ni < 8; ni++) {
            #pragma unroll
            for (int kp = 0; kp < 4; kp++) {
                uint32_t b4[4];
                ldsm4(b4, kb + (uint32_t)((ni * 8 * AST + kp * 16) * 4));
                mma_m16n8k8(s[ni], qf[2 * kp],     b4);
                mma_m16n8k8(s[ni], qf[2 * kp + 1], b4 + 2);
            }
        }

        // ---- online softmax (log2 domain)
        #pragma unroll
        for (int h = 0; h < 2; h++) {
            float mx = -1e30f;
            #pragma unroll
            for (int ni = 0; ni < 8; ni++)
                mx = fmaxf(mx, fmaxf(s[ni][2 * h], s[ni][2 * h + 1]));
            mx = fmaxf(mx, __shfl_xor_sync(0xffffffffu, mx, 1));
            mx = fmaxf(mx, __shfl_xor_sync(0xffffffffu, mx, 2));
            float mnew = fmaxf(m_i[h], mx);
            float corr = exp2f(m_i[h] - mnew);
            float rs = 0.0f;
            #pragma unroll
            for (int ni = 0; ni < 8; ni++) {
                float p0 = exp2f(s[ni][2 * h]     - mnew);
                float p1 = exp2f(s[ni][2 * h + 1] - mnew);
                rs += p0 + p1;
                *(float2*)&wP[h * 8 * AST + ni * 8] = make_float2(tf32r(p0), tf32r(p1));
            }
            rs += __shfl_xor_sync(0xffffffffu, rs, 1);
            rs += __shfl_xor_sync(0xffffffffu, rs, 2);
            l_i[h] = l_i[h] * corr + rs;
            m_i[h] = mnew;
            #pragma unroll
            for (int ni = 0; ni < 8; ni++) {
                o[ni][2 * h]     *= corr;
                o[ni][2 * h + 1] *= corr;
            }
        }

        // ---- store V(t) transposed into buf t&1
        float* Vb_s = Vt + (t & 1) * 64 * AST;
        #pragma unroll
        for (int i = 0; i < 4; i++) {
            int vrw = w4 * 16 + (lane & 15);
            int vs4 = ((lane >> 4) + 2 * wh + 4 * i) * 4;
            Vb_s[(vs4 + 0) * AST + vrw] = vr[i].x;
            Vb_s[(vs4 + 1) * AST + vrw] = vr[i].y;
            Vb_s[(vs4 + 2) * AST + vrw] = vr[i].z;
            Vb_s[(vs4 + 3) * AST + vrw] = vr[i].w;
        }
        __syncthreads();    // all V(t) stores + P stores visible

        // ---- O += P @ V^T
        const uint32_t vb = vAddr + (uint32_t)((t & 1) * 64 * AST * 4);
        uint32_t pf[8][4];
        #pragma unroll
        for (int ki = 0; ki < 8; ki++) ldsm4(pf[ki], qAddr + ki * 32);
        #pragma unroll
        for (int ni = 0; ni < 8; ni++) {
            #pragma unroll
            for (int kp = 0; kp < 4; kp++) {
                uint32_t b4[4];
                ldsm4(b4, vb + (uint32_t)((ni * 8 * AST + kp * 16) * 4));
                mma_m16n8k8(o[ni], pf[2 * kp],     b4);
                mma_m16n8k8(o[ni], pf[2 * kp + 1], b4 + 2);
            }
        }
    }

    // ---- epilogue: normalize, tf32-round, write to g_ctx[B,S,D]
    const int b_idx = bh >> 4;
    const int hh    = bh & 15;
    #pragma unroll
    for (int h = 0; h < 2; h++) {
        float inv = 1.0f / l_i[h];
        int row = q0 + wid * 16 + (lane >> 2) + 8 * h;
        float* dst = g_ctx + ((size_t)b_idx * SEQ + row) * D_MODEL + hh * DK;
        #pragma unroll
        for (int ni = 0; ni < 8; ni++) {
            int col = ni * 8 + (lane & 3) * 2;
            *(float2*)&dst[col] = make_float2(tf32r(o[ni][2 * h] * inv), tf32r(o[ni][2 * h + 1] * inv));
        }
    }
}

// ============================================================================
// Launch
// ============================================================================
extern "C" void kernel_launch(void* const* d_in, const int* in_sizes, int n_in,
                              void* d_out, int out_size)
{
    const float* q  = (const float*)d_in[0];
    const float* k  = (const float*)d_in[1];
    const float* v  = (const float*)d_in[2];
    const float* Wq = (const float*)d_in[3];
    const float* bq = (const float*)d_in[4];
    const float* Wk = (const float*)d_in[5];
    const float* bk = (const float*)d_in[6];
    const float* Wv = (const float*)d_in[7];
    const float* bv = (const float*)d_in[8];
    const float* Wo = (const float*)d_in[9];
    const float* bo = (const float*)d_in[10];
    float* out = (float*)d_out;

    cudaFuncSetAttribute(qkv_tc_kernel,  cudaFuncAttributeMaxDynamicSharedMemorySize, GEMM_SMEM);
    cudaFuncSetAttribute(out_tc_kernel,  cudaFuncAttributeMaxDynamicSharedMemorySize, GEMM_SMEM);
    cudaFuncSetAttribute(attn_tc_kernel, cudaFuncAttributeMaxDynamicSharedMemorySize, ATTN_SMEM);

    dim3 gcvt(296, 7);
    cvt_tf32_kernel<<<gcvt, 256>>>(q, k, v, Wq, Wk, Wv, Wo);

    dim3 gqkv(D_MODEL / 128, TOKENS / 128, 3);
    qkv_tc_kernel<<<gqkv, 256, GEMM_SMEM>>>(bq, bk, bv);

    dim3 gattn(SEQ / 128, BATCH * NHEAD);
    attn_tc_kernel<<<gattn, 256, ATTN_SMEM>>>();

    dim3 gout(D_MODEL / 128, TOKENS / 128);
    out_tc_kernel<<<gout, 256, GEMM_SMEM>>>(bo, out);
}

// round 12
// speedup vs baseline: 3.4911x; 1.0502x over previous
#include <cuda_runtime.h>
#include <cstdint>

#define D_MODEL 1024
#define NHEAD   16
#define DK      64
#define BATCH   2
#define SEQ     2048
#define TOKENS  (BATCH * SEQ)   // 4096
#define NX4     (TOKENS * D_MODEL / 4)
#define NW4     (D_MODEL * D_MODEL / 4)

// ---------------- scratch (device globals; no allocations allowed) ----------
__device__ float g_Qh[BATCH * NHEAD * SEQ * DK];   // [B,H,S,dk] tf32-valued
__device__ float g_Kh[BATCH * NHEAD * SEQ * DK];
__device__ float g_Vh[BATCH * NHEAD * SEQ * DK];
__device__ float g_ctx[TOKENS * D_MODEL];          // [B,S,D] tf32-valued
__device__ float g_X32[3 * TOKENS * D_MODEL];      // q,k,v tf32-rounded
__device__ float g_W32[4 * D_MODEL * D_MODEL];     // Wq,Wk,Wv,Wo tf32-rounded

// ============================================================================
// Helpers (plain sm_80-era PTX only)
// ============================================================================
__device__ __forceinline__ uint32_t smem_u32(const void* p) {
    uint32_t a;
    asm("{ .reg .u64 t; cvta.to.shared.u64 t, %1; cvt.u32.u64 %0, t; }" : "=r"(a) : "l"(p));
    return a;
}
__device__ __forceinline__ uint32_t f2tf32(float f) {
    uint32_t u;
    asm("cvt.rna.tf32.f32 %0, %1;" : "=r"(u) : "f"(f));
    return u;
}
__device__ __forceinline__ float tf32r(float f) { return __uint_as_float(f2tf32(f)); }

__device__ __forceinline__ void cp16(uint32_t dst, const void* src) {
    asm volatile("cp.async.cg.shared.global [%0], [%1], 16;" :: "r"(dst), "l"(src));
}
#define CP_COMMIT() asm volatile("cp.async.commit_group;" ::: "memory")
#define CP_WAIT0()  asm volatile("cp.async.wait_group 0;" ::: "memory")

__device__ __forceinline__ void mma_m16n8k8(float* d, const uint32_t* a, const uint32_t* b) {
    asm volatile(
        "mma.sync.aligned.m16n8k8.row.col.f32.tf32.tf32.f32 "
        "{%0,%1,%2,%3}, {%4,%5,%6,%7}, {%8,%9}, {%0,%1,%2,%3};"
        : "+f"(d[0]), "+f"(d[1]), "+f"(d[2]), "+f"(d[3])
        : "r"(a[0]), "r"(a[1]), "r"(a[2]), "r"(a[3]), "r"(b[0]), "r"(b[1]));
}
__device__ __forceinline__ void ldsm4(uint32_t* r, uint32_t a) {
    asm volatile("ldmatrix.sync.aligned.m8n8.x4.shared.b16 {%0,%1,%2,%3}, [%4];"
                 : "=r"(r[0]), "=r"(r[1]), "=r"(r[2]), "=r"(r[3]) : "r"(a));
}

// ============================================================================
// One-shot tf32 rounding of all GEMM inputs
// ============================================================================
__global__ __launch_bounds__(256) void cvt_tf32_kernel(
    const float* __restrict__ q,  const float* __restrict__ k,  const float* __restrict__ v,
    const float* __restrict__ Wq, const float* __restrict__ Wk,
    const float* __restrict__ Wv, const float* __restrict__ Wo)
{
    const int a = blockIdx.y;
    const float4* src; float4* dst; int n4;
    if (a < 3) {
        src = (const float4*)(a == 0 ? q : a == 1 ? k : v);
        dst = (float4*)(g_X32 + (size_t)a * TOKENS * D_MODEL);
        n4 = NX4;
    } else {
        src = (const float4*)(a == 3 ? Wq : a == 4 ? Wk : a == 5 ? Wv : Wo);
        dst = (float4*)(g_W32 + (size_t)(a - 3) * D_MODEL * D_MODEL);
        n4 = NW4;
    }
    for (int i = blockIdx.x * blockDim.x + threadIdx.x; i < n4; i += gridDim.x * blockDim.x) {
        float4 t = src[i];
        dst[i] = make_float4(tf32r(t.x), tf32r(t.y), tf32r(t.z), tf32r(t.w));
    }
}

// ============================================================================
// tf32 GEMM core: acc = A[m0:+128,:1024] @ B[n0:+128,:1024]^T
// A,B already tf32-valued in gmem. cp.async double buffer, 1 sync per chunk.
// BM=BN=128, BK=32, 256 threads, warp grid 2(m) x 4(n), warp tile 64x32.
// ============================================================================
#define SMEM_STRIDE 36
#define BUF_FLOATS  (128 * SMEM_STRIDE)
#define GEMM_SMEM   (4 * BUF_FLOATS * 4)   // 73728 B

__device__ __forceinline__ void gemm_issue(
    const float* __restrict__ A, const float* __restrict__ B,
    int m0, int n0, int c, int buf, uint32_t sb, int r0, int c4)
{
    const float* Ap = A + (size_t)(m0 + r0) * D_MODEL + c * 32 + c4;
    const float* Bp = B + (size_t)(n0 + r0) * D_MODEL + c * 32 + c4;
    uint32_t dA = sb + (uint32_t)((buf * BUF_FLOATS + r0 * SMEM_STRIDE + c4) * 4);
    uint32_t dB = dA + 2 * BUF_FLOATS * 4;
    #pragma unroll
    for (int i = 0; i < 4; i++) {
        cp16(dA + i * (32 * SMEM_STRIDE * 4), Ap + (size_t)i * 32 * D_MODEL);
        cp16(dB + i * (32 * SMEM_STRIDE * 4), Bp + (size_t)i * 32 * D_MODEL);
    }
}

__device__ __forceinline__ void gemm_cp(
    const float* __restrict__ A, const float* __restrict__ B,
    int m0, int n0, float acc[4][4][4])
{
    extern __shared__ float smf[];
    const uint32_t sb = smem_u32(smf);
    const int tid = threadIdx.x, lane = tid & 31, wid = tid >> 5;
    const int warp_m = wid >> 2, warp_n = wid & 3;
    const int r0 = tid >> 3, c4 = (tid & 7) * 4;

    #pragma unroll
    for (int mi = 0; mi < 4; mi++)
        #pragma unroll
        for (int ni = 0; ni < 4; ni++)
            #pragma unroll
            for (int r = 0; r < 4; r++) acc[mi][ni][r] = 0.0f;

    const int frow = (lane & 7) + ((lane >> 3) & 1) * 8;
    const int fcol = ((lane >> 4) & 1) * 4;
    const uint32_t aAddr = sb + (uint32_t)(((warp_m * 64 + frow) * SMEM_STRIDE + fcol) * 4);
    const uint32_t bAddr = sb + (uint32_t)(2 * BUF_FLOATS * 4)
                         + (uint32_t)(((warp_n * 32 + (lane & 7)) * SMEM_STRIDE + (lane >> 3) * 4) * 4);

    gemm_issue(A, B, m0, n0, 0, 0, sb, r0, c4);
    CP_COMMIT();

    #pragma unroll 1
    for (int c = 0; c < 32; c++) {
        CP_WAIT0();
        __syncthreads();
        if (c + 1 < 32) {
            gemm_issue(A, B, m0, n0, c + 1, (c + 1) & 1, sb, r0, c4);
            CP_COMMIT();
        }
        const uint32_t ab = aAddr + (uint32_t)((c & 1) * BUF_FLOATS * 4);
        const uint32_t bb = bAddr + (uint32_t)((c & 1) * BUF_FLOATS * 4);

        #pragma unroll
        for (int kp = 0; kp < 2; kp++) {
            uint32_t bfr[4][4], af0[4][4], af1[4][4];
            #pragma unroll
            for (int ni = 0; ni < 4; ni++)
                ldsm4(bfr[ni], bb + (uint32_t)((ni * 8 * SMEM_STRIDE + kp * 16) * 4));
            #pragma unroll
            for (int mi = 0; mi < 4; mi++) {
                ldsm4(af0[mi], ab + (uint32_t)((mi * 16 * SMEM_STRIDE + kp * 16) * 4));
                ldsm4(af1[mi], ab + (uint32_t)((mi * 16 * SMEM_STRIDE + kp * 16 + 8) * 4));
            }
            #pragma unroll
            for (int mi = 0; mi < 4; mi++)
                #pragma unroll
                for (int ni = 0; ni < 4; ni++) {
                    mma_m16n8k8(acc[mi][ni], af0[mi], bfr[ni]);
                    mma_m16n8k8(acc[mi][ni], af1[mi], bfr[ni] + 2);
                }
        }
    }
}

// ============================================================================
// QKV projection: Y = X @ W^T + b, head-major tf32-rounded output [B,H,S,dk]
// ============================================================================
__global__ __launch_bounds__(256, 2) void qkv_tc_kernel(
    const float* __restrict__ bq, const float* __restrict__ bk, const float* __restrict__ bv)
{
    const int z = blockIdx.z;
    const float* A = g_X32 + (size_t)z * TOKENS * D_MODEL;
    const float* B = g_W32 + (size_t)z * D_MODEL * D_MODEL;
    const float* bias = (z == 0) ? bq : (z == 1) ? bk : bv;
    float* Y = (z == 0) ? g_Qh : (z == 1) ? g_Kh : g_Vh;

    const int m0 = blockIdx.y * 128;
    const int n0 = blockIdx.x * 128;

    float acc[4][4][4];
    gemm_cp(A, B, m0, n0, acc);

    const int tid = threadIdx.x, lane = tid & 31, wid = tid >> 5;
    const int warp_m = wid >> 2, warp_n = wid & 3;
    const int h = (n0 + warp_n * 32) >> 6;

    #pragma unroll
    for (int mi = 0; mi < 4; mi++) {
        int m_lo = m0 + warp_m * 64 + mi * 16 + (lane >> 2);
        int m_hi = m_lo + 8;
        float* row_lo = Y + (((size_t)(m_lo >> 11) * NHEAD + h) * SEQ + (m_lo & 2047)) * DK;
        float* row_hi = Y + (((size_t)(m_hi >> 11) * NHEAD + h) * SEQ + (m_hi & 2047)) * DK;
        #pragma unroll
        for (int ni = 0; ni < 4; ni++) {
            int colg = n0 + warp_n * 32 + ni * 8 + (lane & 3) * 2;
            float2 bb = *(const float2*)&bias[colg];
            int dkc = colg & 63;
            *(float2*)&row_lo[dkc] = make_float2(tf32r(acc[mi][ni][0] + bb.x), tf32r(acc[mi][ni][1] + bb.y));
            *(float2*)&row_hi[dkc] = make_float2(tf32r(acc[mi][ni][2] + bb.x), tf32r(acc[mi][ni][3] + bb.y));
        }
    }
}

// ============================================================================
// Output projection: out = ctx @ Wo^T + bo  (final output: full fp32)
// ============================================================================
__global__ __launch_bounds__(256, 2) void out_tc_kernel(
    const float* __restrict__ bo, float* __restrict__ out)
{
    const int m0 = blockIdx.y * 128;
    const int n0 = blockIdx.x * 128;

    float acc[4][4][4];
    gemm_cp(g_ctx, g_W32 + (size_t)3 * D_MODEL * D_MODEL, m0, n0, acc);

    const int tid = threadIdx.x, lane = tid & 31, wid = tid >> 5;
    const int warp_m = wid >> 2, warp_n = wid & 3;

    #pragma unroll
    for (int mi = 0; mi < 4; mi++) {
        int m_lo = m0 + warp_m * 64 + mi * 16 + (lane >> 2);
        float* row_lo = out + (size_t)m_lo * D_MODEL;
        float* row_hi = row_lo + 8 * D_MODEL;
        #pragma unroll
        for (int ni = 0; ni < 4; ni++) {
            int colg = n0 + warp_n * 32 + ni * 8 + (lane & 3) * 2;
            float2 bb = *(const float2*)&bo[colg];
            *(float2*)&row_lo[colg] = make_float2(acc[mi][ni][0] + bb.x, acc[mi][ni][1] + bb.y);
            *(float2*)&row_hi[colg] = make_float2(acc[mi][ni][2] + bb.x, acc[mi][ni][3] + bb.y);
        }
    }
}

// ============================================================================
// Flash attention, tf32 mma.sync + ldmatrix. FAT WARP TILES.
// Block = 128 queries of one (b,h), 4 warps (128 threads), warp = 32q x 64k.
// Per K/V fragment ldsm: 4 MMAs (m32) -> K/V smem traffic halved vs 16q warps.
// K via cp.async double-buffered; V reg->smem transpose (conflict-free);
// P per-warp-private, aliases Q staging. exp in log2 domain.
// ============================================================================
#define AST 68
#define ATTN_SMEM ((128 + 128 + 128) * AST * 4)   // P/Q, K x2, Vt x2 = 104448 B

__global__ __launch_bounds__(128, 2) void attn_tc_kernel()
{
    extern __shared__ float sm[];
    float* Ps = sm;                  // [128][AST] — Q staging, then P tiles
    float* Ks = sm + 128 * AST;      // 2 x [64][AST]  [key][dk]
    float* Vt = Ks + 128 * AST;      // 2 x [64][AST]  [dv][key]

    const int tid = threadIdx.x, lane = tid & 31, wid = tid >> 5;   // wid 0..3
    const int bh = blockIdx.y, q0 = blockIdx.x * 128;
    const uint32_t sb = smem_u32(sm);

    const float* Qb = g_Qh + ((size_t)bh * SEQ + q0) * DK;
    const float* Kb = g_Kh + (size_t)bh * SEQ * DK;
    const float* Vb = g_Vh + (size_t)bh * SEQ * DK;

    // ---- Q -> smem, scaled by (1/sqrt(dk)) * log2(e)
    const float QSCALE = 0.18033688011112042f;
    #pragma unroll
    for (int it = 0; it < 16; it++) {
        int idx = tid + it * 128;
        int row = idx >> 4, c4 = (idx & 15) * 4;
        float4 t = *(const float4*)&Qb[(size_t)row * DK + c4];
        *(float4*)&Ps[row * AST + c4] =
            make_float4(tf32r(t.x * QSCALE), tf32r(t.y * QSCALE), tf32r(t.z * QSCALE), tf32r(t.w * QSCALE));
    }

    // ---- issue K tile 0 via cp.async (64 rows x 16 float4; 8 cp16/thread)
    const int krow = tid >> 1, kc16 = (tid & 1) * 8;
    {
        uint32_t dst = sb + (uint32_t)((128 * AST + krow * AST + kc16 * 4) * 4);
        const float* src = Kb + (size_t)krow * DK + kc16 * 4;
        #pragma unroll
        for (int i = 0; i < 8; i++) cp16(dst + i * 16, src + i * 4);
        CP_COMMIT();
    }
    __syncthreads();

    // ---- Q fragments -> registers (loop-invariant): 2 m-frags x 8 k-frags
    const int frow = (lane & 7) + ((lane >> 3) & 1) * 8;
    const int fcol = ((lane >> 4) & 1) * 4;
    const uint32_t pAddr = sb + (uint32_t)(((wid * 32 + frow) * AST + fcol) * 4);
    uint32_t qf[2][8][4];
    #pragma unroll
    for (int mi = 0; mi < 2; mi++)
        #pragma unroll
        for (int ki = 0; ki < 8; ki++)
            ldsm4(qf[mi][ki], pAddr + (uint32_t)(mi * 16 * AST * 4) + ki * 32);

    const uint32_t kAddr = sb + (uint32_t)((128 * AST + (lane & 7) * AST + (lane >> 3) * 4) * 4);
    const uint32_t vAddr = sb + (uint32_t)((256 * AST + (lane & 7) * AST + (lane >> 3) * 4) * 4);

    // V load mapping: rows 32*(wid&1)+lane, dv-cols (wid>>1)*32 .. +31
    const int vrow = 32 * (wid & 1) + lane;
    const int vcb  = (wid >> 1) * 8;     // float4-col base

    float o[2][8][4];
    float m_i[4] = {-1e30f, -1e30f, -1e30f, -1e30f};
    float l_i[4] = {0.0f, 0.0f, 0.0f, 0.0f};
    #pragma unroll
    for (int mi = 0; mi < 2; mi++)
        #pragma unroll
        for (int ni = 0; ni < 8; ni++)
            #pragma unroll
            for (int r = 0; r < 4; r++) o[mi][ni][r] = 0.0f;

    float* wP = Ps + (wid * 32 + (lane >> 2)) * AST + (lane & 3) * 2;

    #pragma unroll 1
    for (int t = 0; t < 32; t++) {
        CP_WAIT0();
        __syncthreads();    // K(t) resident; all warps done reading Vt buf t&1 (from t-2)

        // V(t) -> regs (latency hidden under QK)
        float4 vr[8];
        #pragma unroll
        for (int i = 0; i < 8; i++)
            vr[i] = *(const float4*)&Vb[(size_t)(t * 64 + vrow) * DK + (vcb + i) * 4];

        // issue K(t+1)
        if (t + 1 < 32) {
            uint32_t dst = sb + (uint32_t)((128 * AST + ((t + 1) & 1) * 64 * AST + krow * AST + kc16 * 4) * 4);
            const float* src = Kb + (size_t)((t + 1) * 64 + krow) * DK + kc16 * 4;
            #pragma unroll
            for (int i = 0; i < 8; i++) cp16(dst + i * 16, src + i * 4);
            CP_COMMIT();
        }

        // ---- S = Q K^T (warp tile 32 x 64): 4 MMAs per K ldsm4
        const uint32_t kb = kAddr + (uint32_t)((t & 1) * 64 * AST * 4);
        float s[2][8][4];
        #pragma unroll
        for (int mi = 0; mi < 2; mi++)
            #pragma unroll
            for (int ni = 0; ni < 8; ni++)
                #pragma unroll
                for (int r = 0; r < 4; r++) s[mi][ni][r] = 0.0f;

        #pragma unroll
        for (int ni = 0; ni < 8; ni++) {
            #pragma unroll
            for (int kp = 0; kp < 4; kp++) {
                uint32_t b4[4];
                ldsm4(b4, kb + (uint32_t)((ni * 8 * AST + kp * 16) * 4));
                mma_m16n8k8(s[0][ni], qf[0][2 * kp],     b4);
                mma_m16n8k8(s[0][ni], qf[0][2 * kp + 1], b4 + 2);
                mma_m16n8k8(s[1][ni], qf[1][2 * kp],     b4);
                mma_m16n8k8(s[1][ni], qf[1][2 * kp + 1], b4 + 2);
            }
        }

        // ---- online softmax, 4 row-groups: row = 32w + 16mi + 8r2 + (lane>>2)
        #pragma unroll
        for (int mi = 0; mi < 2; mi++) {
            #pragma unroll
            for (int r2 = 0; r2 < 2; r2++) {
                const int rg = mi * 2 + r2;
                float mx = -1e30f;
                #pragma unroll
                for (int ni = 0; ni < 8; ni++)
                    mx = fmaxf(mx, fmaxf(s[mi][ni][2 * r2], s[mi][ni][2 * r2 + 1]));
                mx = fmaxf(mx, __shfl_xor_sync(0xffffffffu, mx, 1));
                mx = fmaxf(mx, __shfl_xor_sync(0xffffffffu, mx, 2));
                float mnew = fmaxf(m_i[rg], mx);
                float corr = exp2f(m_i[rg] - mnew);
                float rs = 0.0f;
                #pragma unroll
                for (int ni = 0; ni < 8; ni++) {
                    float p0 = exp2f(s[mi][ni][2 * r2]     - mnew);
                    float p1 = exp2f(s[mi][ni][2 * r2 + 1] - mnew);
                    rs += p0 + p1;
                    *(float2*)&wP[(mi * 16 + r2 * 8) * AST + ni * 8] = make_float2(tf32r(p0), tf32r(p1));
                }
                rs += __shfl_xor_sync(0xffffffffu, rs, 1);
                rs += __shfl_xor_sync(0xffffffffu, rs, 2);
                l_i[rg] = l_i[rg] * corr + rs;
                m_i[rg] = mnew;
                #pragma unroll
                for (int ni = 0; ni < 8; ni++) {
                    o[mi][ni][2 * r2]     *= corr;
                    o[mi][ni][2 * r2 + 1] *= corr;
                }
            }
        }

        // ---- store V(t) transposed into buf t&1 (per store: dv fixed, key=lane
        //      => banks = 4*dv + vrow : all 32 lanes distinct, conflict-free)
        float* Vbs = Vt + (t & 1) * 64 * AST;
        #pragma unroll
        for (int i = 0; i < 8; i++) {
            int dv = (vcb + i) * 4;
            Vbs[(dv + 0) * AST + vrow] = vr[i].x;
            Vbs[(dv + 1) * AST + vrow] = vr[i].y;
            Vbs[(dv + 2) * AST + vrow] = vr[i].z;
            Vbs[(dv + 3) * AST + vrow] = vr[i].w;
        }
        __syncthreads();    // V(t) + P(t) stores visible

        // ---- O += P @ V^T : 4 MMAs per V ldsm4
        const uint32_t vb = vAddr + (uint32_t)((t & 1) * 64 * AST * 4);
        uint32_t pf[2][8][4];
        #pragma unroll
        for (int mi = 0; mi < 2; mi++)
            #pragma unroll
            for (int ki = 0; ki < 8; ki++)
                ldsm4(pf[mi][ki], pAddr + (uint32_t)(mi * 16 * AST * 4) + ki * 32);
        #pragma unroll
        for (int ni = 0; ni < 8; ni++) {
            #pragma unroll
            for (int kp = 0; kp < 4; kp++) {
                uint32_t b4[4];
                ldsm4(b4, vb + (uint32_t)((ni * 8 * AST + kp * 16) * 4));
                mma_m16n8k8(o[0][ni], pf[0][2 * kp],     b4);
                mma_m16n8k8(o[0][ni], pf[0][2 * kp + 1], b4 + 2);
                mma_m16n8k8(o[1][ni], pf[1][2 * kp],     b4);
                mma_m16n8k8(o[1][ni], pf[1][2 * kp + 1], b4 + 2);
            }
        }
    }

    // ---- epilogue: normalize, tf32-round, write to g_ctx[B,S,D]
    const int b_idx = bh >> 4;
    const int hh    = bh & 15;
    #pragma unroll
    for (int mi = 0; mi < 2; mi++) {
        #pragma unroll
        for (int r2 = 0; r2 < 2; r2++) {
            const int rg = mi * 2 + r2;
            float inv = 1.0f / l_i[rg];
            int row = q0 + wid * 32 + mi * 16 + r2 * 8 + (lane >> 2);
            float* dst = g_ctx + ((size_t)b_idx * SEQ + row) * D_MODEL + hh * DK;
            #pragma unroll
            for (int ni = 0; ni < 8; ni++) {
                int col = ni * 8 + (lane & 3) * 2;
                *(float2*)&dst[col] = make_float2(tf32r(o[mi][ni][2 * r2] * inv),
                                                  tf32r(o[mi][ni][2 * r2 + 1] * inv));
            }
        }
    }
}

// ============================================================================
// Launch
// ============================================================================
extern "C" void kernel_launch(void* const* d_in, const int* in_sizes, int n_in,
                              void* d_out, int out_size)
{
    const float* q  = (const float*)d_in[0];
    const float* k  = (const float*)d_in[1];
    const float* v  = (const float*)d_in[2];
    const float* Wq = (const float*)d_in[3];
    const float* bq = (const float*)d_in[4];
    const float* Wk = (const float*)d_in[5];
    const float* bk = (const float*)d_in[6];
    const float* Wv = (const float*)d_in[7];
    const float* bv = (const float*)d_in[8];
    const float* Wo = (const float*)d_in[9];
    const float* bo = (const float*)d_in[10];
    float* out = (float*)d_out;

    cudaFuncSetAttribute(qkv_tc_kernel,  cudaFuncAttributeMaxDynamicSharedMemorySize, GEMM_SMEM);
    cudaFuncSetAttribute(out_tc_kernel,  cudaFuncAttributeMaxDynamicSharedMemorySize, GEMM_SMEM);
    cudaFuncSetAttribute(attn_tc_kernel, cudaFuncAttributeMaxDynamicSharedMemorySize, ATTN_SMEM);

    dim3 gcvt(296, 7);
    cvt_tf32_kernel<<<gcvt, 256>>>(q, k, v, Wq, Wk, Wv, Wo);

    dim3 gqkv(D_MODEL / 128, TOKENS / 128, 3);
    qkv_tc_kernel<<<gqkv, 256, GEMM_SMEM>>>(bq, bk, bv);

    dim3 gattn(SEQ / 128, BATCH * NHEAD);
    attn_tc_kernel<<<gattn, 128, ATTN_SMEM>>>();

    dim3 gout(D_MODEL / 128, TOKENS / 128);
    out_tc_kernel<<<gout, 256, GEMM_SMEM>>>(bo, out);
}